// round 9
// baseline (speedup 1.0000x reference)
#include <cuda_runtime.h>
#include <cuda_bf16.h>
#include <cuda_fp16.h>
#include <math.h>
#include <cstdint>

#define SEQ 2048
#define HID 2048
#define KVD 512
#define QKVN 3072
#define NQH 32
#define NKH 8

// ---------------- scratch (no allocations allowed) ----------------
__device__ float g_QKV[SEQ * QKVN];
__device__ __nv_bfloat16 g_Ahi[SEQ * HID];
__device__ __nv_bfloat16 g_Alo[SEQ * HID];
__device__ __half g_Ohf[SEQ * HID];
__device__ __half g_Olf[SEQ * HID];
__device__ __nv_bfloat16 g_Whi[QKVN * HID];   // transposed q|k|v weights [N,K] bf16
__device__ __nv_bfloat16 g_Wlo[QKVN * HID];
__device__ __half g_Woh[HID * HID];           // transposed o weights, fp16 hi only
__device__ __nv_bfloat16 g_Khi[SEQ * KVD];
__device__ __nv_bfloat16 g_Klo[SEQ * KVD];
__device__ __half g_Vh[SEQ * KVD];            // V fp16 hi only
__device__ float2 g_sc[SEQ * 32];             // sincos LUT

// ---------------- helpers ----------------
__device__ __forceinline__ uint32_t smem_u32(const void* p) {
    uint32_t a;
    asm("{ .reg .u64 t; cvta.to.shared.u64 t, %1; cvt.u32.u64 %0, t; }" : "=r"(a) : "l"(p));
    return a;
}

#define LDSM4(r0, r1, r2, r3, addr) \
    asm volatile("ldmatrix.sync.aligned.m8n8.x4.shared.b16 {%0,%1,%2,%3}, [%4];" \
        : "=r"(r0), "=r"(r1), "=r"(r2), "=r"(r3) : "r"(addr))

#define LDSM4T(r0, r1, r2, r3, addr) \
    asm volatile("ldmatrix.sync.aligned.m8n8.x4.trans.shared.b16 {%0,%1,%2,%3}, [%4];" \
        : "=r"(r0), "=r"(r1), "=r"(r2), "=r"(r3) : "r"(addr))

#define MMA16816(d, a, b0, b1) \
    asm volatile("mma.sync.aligned.m16n8k16.row.col.f32.bf16.bf16.f32 " \
        "{%0,%1,%2,%3},{%4,%5,%6,%7},{%8,%9},{%0,%1,%2,%3};" \
        : "+f"((d)[0]), "+f"((d)[1]), "+f"((d)[2]), "+f"((d)[3]) \
        : "r"((a)[0]), "r"((a)[1]), "r"((a)[2]), "r"((a)[3]), "r"(b0), "r"(b1))

#define MMA16816F(d, a, b0, b1) \
    asm volatile("mma.sync.aligned.m16n8k16.row.col.f32.f16.f16.f32 " \
        "{%0,%1,%2,%3},{%4,%5,%6,%7},{%8,%9},{%0,%1,%2,%3};" \
        : "+f"((d)[0]), "+f"((d)[1]), "+f"((d)[2]), "+f"((d)[3]) \
        : "r"((a)[0]), "r"((a)[1]), "r"((a)[2]), "r"((a)[3]), "r"(b0), "r"(b1))

#define CP_ASYNC16(dst, src) \
    asm volatile("cp.async.cg.shared.global [%0], [%1], 16;" :: "r"(dst), "l"(src))
#define CP_COMMIT() asm volatile("cp.async.commit_group;" ::: "memory")
#define CP_WAIT0()  asm volatile("cp.async.wait_group 0;" ::: "memory")
#define CP_WAIT1()  asm volatile("cp.async.wait_group 1;" ::: "memory")

// ---------------- elementwise kernels ----------------
__device__ __forceinline__ uint32_t pack_bf2(__nv_bfloat16 a, __nv_bfloat16 b) {
    __nv_bfloat162 t(a, b);
    return *reinterpret_cast<uint32_t*>(&t);
}

__global__ __launch_bounds__(256) void convert_hl(const float* __restrict__ X,
                                                  __nv_bfloat16* __restrict__ hi,
                                                  __nv_bfloat16* __restrict__ lo) {
    int i = blockIdx.x * 256 + threadIdx.x;
    float4 v = *(const float4*)(X + (size_t)i * 4);
    __nv_bfloat16 h0 = __float2bfloat16_rn(v.x), h1 = __float2bfloat16_rn(v.y);
    __nv_bfloat16 h2 = __float2bfloat16_rn(v.z), h3 = __float2bfloat16_rn(v.w);
    __nv_bfloat16 l0 = __float2bfloat16_rn(v.x - __bfloat162float(h0));
    __nv_bfloat16 l1 = __float2bfloat16_rn(v.y - __bfloat162float(h1));
    __nv_bfloat16 l2 = __float2bfloat16_rn(v.z - __bfloat162float(h2));
    __nv_bfloat16 l3 = __float2bfloat16_rn(v.w - __bfloat162float(h3));
    *(uint2*)(hi + (size_t)i * 4) = make_uint2(pack_bf2(h0, h1), pack_bf2(h2, h3));
    *(uint2*)(lo + (size_t)i * 4) = make_uint2(pack_bf2(l0, l1), pack_bf2(l2, l3));
}

// strided fp32 -> fp16 (hi only) for V
__global__ __launch_bounds__(256) void convert_h16_strided(const float* __restrict__ X,
                                                           __half* __restrict__ h,
                                                           int ld, int col0, int cols) {
    int i = blockIdx.x * 256 + threadIdx.x;
    int r = i / (cols / 4), q = i % (cols / 4);
    float4 v = *(const float4*)(X + (size_t)r * ld + col0 + q * 4);
    __half2 a = __floats2half2_rn(v.x, v.y);
    __half2 b = __floats2half2_rn(v.z, v.w);
    *(uint2*)(h + (size_t)r * cols + q * 4) =
        make_uint2(*reinterpret_cast<uint32_t*>(&a), *reinterpret_cast<uint32_t*>(&b));
}

// fused transpose: q,k,v -> bf16 hi/lo into Whi/Wlo; o -> fp16 hi into Woh
__global__ __launch_bounds__(256) void transpose_all(const float* __restrict__ Wq,
                                                     const float* __restrict__ Wk,
                                                     const float* __restrict__ Wv,
                                                     const float* __restrict__ Wo,
                                                     __nv_bfloat16* __restrict__ thi,
                                                     __nv_bfloat16* __restrict__ tlo,
                                                     __half* __restrict__ toh) {
    __shared__ float t[32][33];
    int bx = blockIdx.x;
    const float* W;
    int N, nblk, dstoff;
    bool is_o = false;
    if (bx < 64)       { W = Wq; N = HID; nblk = bx;      dstoff = 0; }
    else if (bx < 80)  { W = Wk; N = KVD; nblk = bx - 64; dstoff = HID; }
    else if (bx < 96)  { W = Wv; N = KVD; nblk = bx - 80; dstoff = HID + KVD; }
    else               { W = Wo; N = HID; nblk = bx - 96; dstoff = 0; is_o = true; }
    int tx = threadIdx.x & 31, ty = threadIdx.x >> 5;
    int k0 = blockIdx.y * 32, n0 = nblk * 32;
#pragma unroll
    for (int i = 0; i < 4; i++)
        t[ty + i * 8][tx] = W[(size_t)(k0 + ty + i * 8) * N + n0 + tx];
    __syncthreads();
#pragma unroll
    for (int i = 0; i < 4; i++) {
        float v = t[tx][ty + i * 8];
        size_t o = (size_t)(dstoff + n0 + ty + i * 8) * HID + k0 + tx;
        if (is_o) {
            toh[o] = __float2half_rn(v);
        } else {
            __nv_bfloat16 h = __float2bfloat16_rn(v);
            thi[o] = h;
            tlo[o] = __float2bfloat16_rn(v - __bfloat162float(h));
        }
    }
}

// sincos LUT init
__global__ __launch_bounds__(256) void sc_init(const float* __restrict__ inv_freq,
                                               float2* __restrict__ sc) {
    int i = blockIdx.x * 256 + threadIdx.x;
    int s = i >> 5, j = i & 31;
    float angle = (float)s * inv_freq[j];
    sc[i] = make_float2(sinf(angle), cosf(angle));
}

// RoPE + scale + bf16 hi/lo split, using LUT
__global__ __launch_bounds__(256) void rope_conv(const float* __restrict__ X,
                                                 __nv_bfloat16* __restrict__ hi,
                                                 __nv_bfloat16* __restrict__ lo,
                                                 const float2* __restrict__ sc,
                                                 int heads, float scale, int ld, int col0) {
    int idx = blockIdx.x * 8 + (threadIdx.x >> 5);
    int j = threadIdx.x & 31;
    int s = idx / heads;
    int h = idx - s * heads;
    const float* p = X + (size_t)s * ld + col0 + h * 64;
    float2 snc = sc[s * 32 + j];
    float a = p[j], b = p[32 + j];
    float r0 = (a * snc.y + b * snc.x) * scale;
    float r1 = (a * snc.x - b * snc.y) * scale;
    size_t o = (size_t)s * heads * 64 + h * 64;
    __nv_bfloat16 h0 = __float2bfloat16_rn(r0);
    __nv_bfloat16 h1 = __float2bfloat16_rn(r1);
    hi[o + j] = h0;
    hi[o + 32 + j] = h1;
    lo[o + j] = __float2bfloat16_rn(r0 - __bfloat162float(h0));
    lo[o + 32 + j] = __float2bfloat16_rn(r1 - __bfloat162float(h1));
}

// ---------------- bf16 3-pass GEMM (QKV): 64x128 tile, occ 3 ----------------
// Per buffer: Ahi(0,5120) Alo(5120) Bhi(10240,10240) Blo(20480) => 30720 bytes
#define ABUF 5120
#define QBUF 30720
#define G_SMEM (2 * QBUF)

// 128-row tile loader (2 ops/thread)
__device__ __forceinline__ void tile_async128(uint32_t dst, const void* src_,
                                              int ldk, int tid) {
    const __nv_bfloat16* src = (const __nv_bfloat16*)src_;
#pragma unroll
    for (int t = 0; t < 2; t++) {
        int i = tid + t * 256;
        int r = i >> 2, q = i & 3;
        CP_ASYNC16(dst + r * 80 + q * 16, src + (size_t)r * ldk + q * 8);
    }
}
// 64-row tile loader (1 op/thread)
__device__ __forceinline__ void tile_async64(uint32_t dst, const void* src_,
                                             int ldk, int tid) {
    const __nv_bfloat16* src = (const __nv_bfloat16*)src_;
    int r = tid >> 2, q = tid & 3;
    CP_ASYNC16(dst + r * 80 + q * 16, src + (size_t)r * ldk + q * 8);
}

__global__ __launch_bounds__(256, 3) void gemm_mma(
    const __nv_bfloat16* __restrict__ Ahi, const __nv_bfloat16* __restrict__ Alo,
    const __nv_bfloat16* __restrict__ Bhi, const __nv_bfloat16* __restrict__ Blo,
    float* __restrict__ C, int M, int N, int K) {
    extern __shared__ char smem[];
    const uint32_t sb = smem_u32(smem);
    const int tid = threadIdx.x;
    const int w = tid >> 5;
    const int lane = tid & 31;
    const int wm = (w & 1) * 32;      // 2 warps in M (64 rows)
    const int wn = (w >> 1) * 32;     // 4 warps in N (128 cols)
    const int m0 = blockIdx.y * 64;
    const int n0 = blockIdx.x * 128;

    const int a_row = lane & 15;
    const int a_kh = (lane >> 4) & 1;
    const int b_n = (lane & 7) + ((lane >> 4) << 3);
    const int b_kh = (lane >> 3) & 1;

    float acc[2][4][4];
#pragma unroll
    for (int i = 0; i < 2; i++)
#pragma unroll
        for (int j = 0; j < 4; j++)
#pragma unroll
            for (int r = 0; r < 4; r++) acc[i][j][r] = 0.f;

    const int NC = K >> 5;
    {
        const size_t ak = (size_t)m0 * K;
        const size_t bk = (size_t)n0 * K;
        tile_async64(sb,           Ahi + ak, K, tid);
        tile_async64(sb + ABUF,    Alo + ak, K, tid);
        tile_async128(sb + 2 * ABUF,         Bhi + bk, K, tid);
        tile_async128(sb + 2 * ABUF + 10240, Blo + bk, K, tid);
        CP_COMMIT();
    }

    for (int c = 0; c < NC; c++) {
        CP_WAIT0();
        __syncthreads();
        if (c + 1 < NC) {
            const uint32_t nb = sb + ((c + 1) & 1) * QBUF;
            const size_t ak = (size_t)m0 * K + (size_t)(c + 1) * 32;
            const size_t bk = (size_t)n0 * K + (size_t)(c + 1) * 32;
            tile_async64(nb,           Ahi + ak, K, tid);
            tile_async64(nb + ABUF,    Alo + ak, K, tid);
            tile_async128(nb + 2 * ABUF,         Bhi + bk, K, tid);
            tile_async128(nb + 2 * ABUF + 10240, Blo + bk, K, tid);
            CP_COMMIT();
        }
        const uint32_t base = sb + (c & 1) * QBUF;

#pragma unroll
        for (int ks = 0; ks < 32; ks += 16) {
            uint32_t ah[2][4], al[2][4], bh[2][4], bl[2][4];
            const uint32_t aoff = (uint32_t)((wm + a_row) * 80 + (ks + a_kh * 8) * 2);
            const uint32_t boff = (uint32_t)((wn + b_n) * 80 + (ks + b_kh * 8) * 2);
#pragma unroll
            for (int mt = 0; mt < 2; mt++) {
                LDSM4(ah[mt][0], ah[mt][1], ah[mt][2], ah[mt][3],
                      base + aoff + mt * 16 * 80);
                LDSM4(al[mt][0], al[mt][1], al[mt][2], al[mt][3],
                      base + ABUF + aoff + mt * 16 * 80);
            }
#pragma unroll
            for (int np = 0; np < 2; np++) {
                LDSM4(bh[np][0], bh[np][1], bh[np][2], bh[np][3],
                      base + 2 * ABUF + boff + np * 16 * 80);
                LDSM4(bl[np][0], bl[np][1], bl[np][2], bl[np][3],
                      base + 2 * ABUF + 10240 + boff + np * 16 * 80);
            }
            // pass-major
#pragma unroll
            for (int mt = 0; mt < 2; mt++)
#pragma unroll
                for (int np = 0; np < 2; np++) {
                    MMA16816(acc[mt][np * 2 + 0], ah[mt], bh[np][0], bh[np][1]);
                    MMA16816(acc[mt][np * 2 + 1], ah[mt], bh[np][2], bh[np][3]);
                }
#pragma unroll
            for (int mt = 0; mt < 2; mt++)
#pragma unroll
                for (int np = 0; np < 2; np++) {
                    MMA16816(acc[mt][np * 2 + 0], ah[mt], bl[np][0], bl[np][1]);
                    MMA16816(acc[mt][np * 2 + 1], ah[mt], bl[np][2], bl[np][3]);
                }
#pragma unroll
            for (int mt = 0; mt < 2; mt++)
#pragma unroll
                for (int np = 0; np < 2; np++) {
                    MMA16816(acc[mt][np * 2 + 0], al[mt], bh[np][0], bh[np][1]);
                    MMA16816(acc[mt][np * 2 + 1], al[mt], bh[np][2], bh[np][3]);
                }
        }
    }

    const int g = lane >> 2, c2 = lane & 3;
#pragma unroll
    for (int mt = 0; mt < 2; mt++) {
        const int row = m0 + wm + mt * 16 + g;
#pragma unroll
        for (int nt = 0; nt < 4; nt++) {
            const int col = n0 + wn + nt * 8 + c2 * 2;
            *(float2*)&C[(size_t)row * N + col] =
                make_float2(acc[mt][nt][0], acc[mt][nt][1]);
            *(float2*)&C[(size_t)(row + 8) * N + col] =
                make_float2(acc[mt][nt][2], acc[mt][nt][3]);
        }
    }
}

// ---------------- fp16 2-pass GEMM (O projection), 128x128 occ 2 ----------------
#define TILE_B 10240
#define BUF2_B 30720
#define G2_SMEM (2 * BUF2_B)

__global__ __launch_bounds__(256, 2) void gemm_mma2(
    const __half* __restrict__ Ahi, const __half* __restrict__ Alo,
    const __half* __restrict__ Bh,
    float* __restrict__ C, int M, int N, int K) {
    extern __shared__ char smem[];
    const uint32_t sb = smem_u32(smem);
    const int tid = threadIdx.x;
    const int w = tid >> 5;
    const int lane = tid & 31;
    const int wm = (w & 1) * 64;
    const int wn = (w >> 1) * 32;
    const int m0 = blockIdx.y * 128;
    const int n0 = blockIdx.x * 128;

    const int a_row = lane & 15;
    const int a_kh = (lane >> 4) & 1;
    const int b_n = (lane & 7) + ((lane >> 4) << 3);
    const int b_kh = (lane >> 3) & 1;

    float acc[4][4][4];
#pragma unroll
    for (int i = 0; i < 4; i++)
#pragma unroll
        for (int j = 0; j < 4; j++)
#pragma unroll
            for (int r = 0; r < 4; r++) acc[i][j][r] = 0.f;

    const int NC = K >> 5;
    {
        const size_t ak = (size_t)m0 * K;
        const size_t bk = (size_t)n0 * K;
        tile_async128(sb,              Ahi + ak, K, tid);
        tile_async128(sb + TILE_B,     Alo + ak, K, tid);
        tile_async128(sb + 2 * TILE_B, Bh + bk, K, tid);
        CP_COMMIT();
    }

    for (int c = 0; c < NC; c++) {
        CP_WAIT0();
        __syncthreads();
        if (c + 1 < NC) {
            const uint32_t nb = sb + ((c + 1) & 1) * BUF2_B;
            const size_t ak = (size_t)m0 * K + (size_t)(c + 1) * 32;
            const size_t bk = (size_t)n0 * K + (size_t)(c + 1) * 32;
            tile_async128(nb,              Ahi + ak, K, tid);
            tile_async128(nb + TILE_B,     Alo + ak, K, tid);
            tile_async128(nb + 2 * TILE_B, Bh + bk, K, tid);
            CP_COMMIT();
        }
        const uint32_t base = sb + (c & 1) * BUF2_B;

#pragma unroll
        for (int ks = 0; ks < 32; ks += 16) {
            uint32_t ah[4][4], al[4][4], bh[2][4];
            const uint32_t aoff = (uint32_t)((wm + a_row) * 80 + (ks + a_kh * 8) * 2);
            const uint32_t boff = (uint32_t)((wn + b_n) * 80 + (ks + b_kh * 8) * 2);
#pragma unroll
            for (int mt = 0; mt < 4; mt++) {
                LDSM4(ah[mt][0], ah[mt][1], ah[mt][2], ah[mt][3],
                      base + aoff + mt * 16 * 80);
                LDSM4(al[mt][0], al[mt][1], al[mt][2], al[mt][3],
                      base + TILE_B + aoff + mt * 16 * 80);
            }
#pragma unroll
            for (int np = 0; np < 2; np++)
                LDSM4(bh[np][0], bh[np][1], bh[np][2], bh[np][3],
                      base + 2 * TILE_B + boff + np * 16 * 80);
#pragma unroll
            for (int mt = 0; mt < 4; mt++)
#pragma unroll
                for (int np = 0; np < 2; np++) {
                    MMA16816F(acc[mt][np * 2 + 0], ah[mt], bh[np][0], bh[np][1]);
                    MMA16816F(acc[mt][np * 2 + 1], ah[mt], bh[np][2], bh[np][3]);
                }
#pragma unroll
            for (int mt = 0; mt < 4; mt++)
#pragma unroll
                for (int np = 0; np < 2; np++) {
                    MMA16816F(acc[mt][np * 2 + 0], al[mt], bh[np][0], bh[np][1]);
                    MMA16816F(acc[mt][np * 2 + 1], al[mt], bh[np][2], bh[np][3]);
                }
        }
    }

    const int g = lane >> 2, c2 = lane & 3;
#pragma unroll
    for (int mt = 0; mt < 4; mt++) {
        const int row = m0 + wm + mt * 16 + g;
#pragma unroll
        for (int nt = 0; nt < 4; nt++) {
            const int col = n0 + wn + nt * 8 + c2 * 2;
            *(float2*)&C[(size_t)row * N + col] =
                make_float2(acc[mt][nt][0], acc[mt][nt][1]);
            *(float2*)&C[(size_t)(row + 8) * N + col] =
                make_float2(acc[mt][nt][2], acc[mt][nt][3]);
        }
    }
}

// ---------------- tensor-core flash attention (unchanged) ----------------
#define FQ_H 0
#define FQ_L 18432
#define FKV  36864
#define FKV_STRIDE 27648
#define F_SMEM 92160

__device__ __forceinline__ void pack_hl16(float p0, float p1, uint32_t& hi, uint32_t& lo) {
    __half2 h = __floats2half2_rn(p0, p1);
    hi = *reinterpret_cast<uint32_t*>(&h);
    __half2 l = __floats2half2_rn(p0 - __half2float(__low2half(h)),
                                  p1 - __half2float(__high2half(h)));
    lo = *reinterpret_cast<uint32_t*>(&l);
}

__global__ __launch_bounds__(256, 2) void flash_mma(
    const __nv_bfloat16* __restrict__ Qhi, const __nv_bfloat16* __restrict__ Qlo,
    const __nv_bfloat16* __restrict__ Khi, const __nv_bfloat16* __restrict__ Klo,
    const __half* __restrict__ Vh,
    __half* __restrict__ Ohf, __half* __restrict__ Olf) {
    extern __shared__ char smem[];
    const uint32_t sb = smem_u32(smem);
    const int tid = threadIdx.x;
    const int lane = tid & 31;
    const int w = tid >> 5;
    const int ib = gridDim.x - 1 - blockIdx.x;
    const int qh = blockIdx.y;
    const int kh = qh >> 2;
    const int qbase = ib * 128;

#pragma unroll
    for (int i = 0; i < 8; i++) {
        int idx = tid + i * 256;
        int sub = idx >> 10, r = (idx >> 3) & 127, q = idx & 7;
        const __nv_bfloat16* src = (sub ? Qlo : Qhi) + (size_t)(qbase + r) * HID + qh * 64 + q * 8;
        CP_ASYNC16(sb + sub * 18432 + r * 144 + q * 16, src);
    }
    CP_COMMIT();

#pragma unroll
    for (int i = 0; i < 6; i++) {
        int idx = tid + i * 256;
        int sub = idx >> 9, r = (idx >> 3) & 63, q = idx & 7;
        const uint16_t* base = (sub == 0) ? (const uint16_t*)Khi
                               : (sub == 1) ? (const uint16_t*)Klo : (const uint16_t*)Vh;
        const void* src = base + (size_t)r * KVD + kh * 64 + q * 8;
        CP_ASYNC16(sb + FKV + sub * 9216 + r * 144 + q * 16, src);
    }
    CP_COMMIT();

    const int a_row = lane & 15, a_kh = lane >> 4;
    const int b_n = (lane & 7) + ((lane >> 4) << 3), b_kh = (lane >> 3) & 1;
    const int v_k = (lane & 7) + ((lane >> 3) & 1) * 8, v_n = (lane >> 4) * 8;
    const int g = lane >> 2, tg = lane & 3;

    float o[8][4];
#pragma unroll
    for (int nt = 0; nt < 8; nt++)
#pragma unroll
        for (int r = 0; r < 4; r++) o[nt][r] = 0.f;
    float m0 = -1e30f, m1 = -1e30f, l0 = 0.f, l1 = 0.f;

    const int jbmax = 2 * ib + 1;
    for (int jb = 0; jb <= jbmax; jb++) {
        const uint32_t kvb = sb + FKV + (jb & 1) * FKV_STRIDE;
        __syncthreads();
        if (jb < jbmax) {
            const uint32_t nb = sb + FKV + ((jb + 1) & 1) * FKV_STRIDE;
#pragma unroll
            for (int i = 0; i < 6; i++) {
                int idx = tid + i * 256;
                int sub = idx >> 9, r = (idx >> 3) & 63, q = idx & 7;
                const uint16_t* base = (sub == 0) ? (const uint16_t*)Khi
                                       : (sub == 1) ? (const uint16_t*)Klo : (const uint16_t*)Vh;
                const void* src = base + (size_t)((jb + 1) * 64 + r) * KVD + kh * 64 + q * 8;
                CP_ASYNC16(nb + sub * 9216 + r * 144 + q * 16, src);
            }
            CP_COMMIT();
            CP_WAIT1();
        } else {
            CP_WAIT0();
        }
        __syncthreads();

        // S = Q K^T (bf16 3-pass, pass-major)
        float s[8][4];
#pragma unroll
        for (int nt = 0; nt < 8; nt++)
#pragma unroll
            for (int r = 0; r < 4; r++) s[nt][r] = 0.f;
#pragma unroll
        for (int kc = 0; kc < 4; kc++) {
            uint32_t ah[4], al[4];
            const uint32_t aoff = (w * 16 + a_row) * 144 + (kc * 16 + a_kh * 8) * 2;
            LDSM4(ah[0], ah[1], ah[2], ah[3], sb + FQ_H + aoff);
            LDSM4(al[0], al[1], al[2], al[3], sb + FQ_L + aoff);
#pragma unroll
            for (int n2p = 0; n2p < 2; n2p++) {
                uint32_t bh[2][4], bl[2][4];
#pragma unroll
                for (int j = 0; j < 2; j++) {
                    const int n2 = n2p * 2 + j;
                    const uint32_t boff = (n2 * 16 + b_n) * 144 + (kc * 16 + b_kh * 8) * 2;
                    LDSM4(bh[j][0], bh[j][1], bh[j][2], bh[j][3], kvb + boff);
                    LDSM4(bl[j][0], bl[j][1], bl[j][2], bl[j][3], kvb + 9216 + boff);
                }
#pragma unroll
                for (int j = 0; j < 2; j++) {
                    const int n2 = n2p * 2 + j;
                    MMA16816(s[n2 * 2 + 0], ah, bh[j][0], bh[j][1]);
                    MMA16816(s[n2 * 2 + 1], ah, bh[j][2], bh[j][3]);
                }
#pragma unroll
                for (int j = 0; j < 2; j++) {
                    const int n2 = n2p * 2 + j;
                    MMA16816(s[n2 * 2 + 0], ah, bl[j][0], bl[j][1]);
                    MMA16816(s[n2 * 2 + 1], ah, bl[j][2], bl[j][3]);
                }
#pragma unroll
                for (int j = 0; j < 2; j++) {
                    const int n2 = n2p * 2 + j;
                    MMA16816(s[n2 * 2 + 0], al, bh[j][0], bh[j][1]);
                    MMA16816(s[n2 * 2 + 1], al, bh[j][2], bh[j][3]);
                }
            }
        }

        if (jb >= 2 * ib) {
            const int row0 = qbase + w * 16 + g;
            const int row1 = row0 + 8;
#pragma unroll
            for (int nt = 0; nt < 8; nt++) {
                const int col = jb * 64 + nt * 8 + tg * 2;
                if (col > row0) s[nt][0] = -1e30f;
                if (col + 1 > row0) s[nt][1] = -1e30f;
                if (col > row1) s[nt][2] = -1e30f;
                if (col + 1 > row1) s[nt][3] = -1e30f;
            }
        }

        float mx0 = -1e30f, mx1 = -1e30f;
#pragma unroll
        for (int nt = 0; nt < 8; nt++) {
            mx0 = fmaxf(mx0, fmaxf(s[nt][0], s[nt][1]));
            mx1 = fmaxf(mx1, fmaxf(s[nt][2], s[nt][3]));
        }
        mx0 = fmaxf(mx0, __shfl_xor_sync(0xffffffff, mx0, 1));
        mx0 = fmaxf(mx0, __shfl_xor_sync(0xffffffff, mx0, 2));
        mx1 = fmaxf(mx1, __shfl_xor_sync(0xffffffff, mx1, 1));
        mx1 = fmaxf(mx1, __shfl_xor_sync(0xffffffff, mx1, 2));
        const float mn0 = fmaxf(m0, mx0), mn1 = fmaxf(m1, mx1);
        const float al0 = __expf(m0 - mn0), al1 = __expf(m1 - mn1);
        m0 = mn0; m1 = mn1;

        float rs0 = 0.f, rs1 = 0.f;
#pragma unroll
        for (int nt = 0; nt < 8; nt++) {
            s[nt][0] = __expf(s[nt][0] - mn0);
            s[nt][1] = __expf(s[nt][1] - mn0);
            s[nt][2] = __expf(s[nt][2] - mn1);
            s[nt][3] = __expf(s[nt][3] - mn1);
            rs0 += s[nt][0] + s[nt][1];
            rs1 += s[nt][2] + s[nt][3];
            o[nt][0] *= al0; o[nt][1] *= al0;
            o[nt][2] *= al1; o[nt][3] *= al1;
        }
        rs0 += __shfl_xor_sync(0xffffffff, rs0, 1);
        rs0 += __shfl_xor_sync(0xffffffff, rs0, 2);
        rs1 += __shfl_xor_sync(0xffffffff, rs1, 1);
        rs1 += __shfl_xor_sync(0xffffffff, rs1, 2);
        l0 = l0 * al0 + rs0;
        l1 = l1 * al1 + rs1;

        // O += P @ V : fp16 2-pass
#pragma unroll
        for (int kc2 = 0; kc2 < 4; kc2++) {
            uint32_t aph[4], apl[4];
            pack_hl16(s[2 * kc2][0], s[2 * kc2][1], aph[0], apl[0]);
            pack_hl16(s[2 * kc2][2], s[2 * kc2][3], aph[1], apl[1]);
            pack_hl16(s[2 * kc2 + 1][0], s[2 * kc2 + 1][1], aph[2], apl[2]);
            pack_hl16(s[2 * kc2 + 1][2], s[2 * kc2 + 1][3], aph[3], apl[3]);
#pragma unroll
            for (int n2p = 0; n2p < 2; n2p++) {
                uint32_t vh[2][4];
#pragma unroll
                for (int j = 0; j < 2; j++) {
                    const int n2 = n2p * 2 + j;
                    const uint32_t voff = (kc2 * 16 + v_k) * 144 + (n2 * 16 + v_n) * 2;
                    LDSM4T(vh[j][0], vh[j][1], vh[j][2], vh[j][3], kvb + 2 * 9216 + voff);
                }
#pragma unroll
                for (int j = 0; j < 2; j++) {
                    const int n2 = n2p * 2 + j;
                    MMA16816F(o[n2 * 2 + 0], aph, vh[j][0], vh[j][1]);
                    MMA16816F(o[n2 * 2 + 1], aph, vh[j][2], vh[j][3]);
                }
#pragma unroll
                for (int j = 0; j < 2; j++) {
                    const int n2 = n2p * 2 + j;
                    MMA16816F(o[n2 * 2 + 0], apl, vh[j][0], vh[j][1]);
                    MMA16816F(o[n2 * 2 + 1], apl, vh[j][2], vh[j][3]);
                }
            }
        }
    }

    const float il0 = 1.0f / l0, il1 = 1.0f / l1;
    const int row0 = qbase + w * 16 + g;
#pragma unroll
    for (int nt = 0; nt < 8; nt++) {
        const int col = qh * 64 + nt * 8 + tg * 2;
        uint32_t h, l;
        pack_hl16(o[nt][0] * il0, o[nt][1] * il0, h, l);
        *(uint32_t*)&Ohf[(size_t)row0 * HID + col] = h;
        *(uint32_t*)&Olf[(size_t)row0 * HID + col] = l;
        pack_hl16(o[nt][2] * il1, o[nt][3] * il1, h, l);
        *(uint32_t*)&Ohf[(size_t)(row0 + 8) * HID + col] = h;
        *(uint32_t*)&Olf[(size_t)(row0 + 8) * HID + col] = l;
    }
}

// ---------------------------------------------------------------------------
extern "C" void kernel_launch(void* const* d_in, const int* in_sizes, int n_in,
                              void* d_out, int out_size) {
    const float* x        = (const float*)d_in[0];
    const float* q_proj   = (const float*)d_in[1];
    const float* k_proj   = (const float*)d_in[2];
    const float* v_proj   = (const float*)d_in[3];
    const float* o_proj   = (const float*)d_in[4];
    const float* inv_freq = (const float*)d_in[5];
    float* out = (float*)d_out;

    float *QKVb;
    __nv_bfloat16 *Ahi, *Alo, *Whi, *Wlo, *Khi, *Klo;
    __half *Ohf, *Olf, *Woh, *Vh;
    float2* sc;
    cudaGetSymbolAddress((void**)&QKVb, g_QKV);
    cudaGetSymbolAddress((void**)&Ahi, g_Ahi);
    cudaGetSymbolAddress((void**)&Alo, g_Alo);
    cudaGetSymbolAddress((void**)&Ohf, g_Ohf);
    cudaGetSymbolAddress((void**)&Olf, g_Olf);
    cudaGetSymbolAddress((void**)&Whi, g_Whi);
    cudaGetSymbolAddress((void**)&Wlo, g_Wlo);
    cudaGetSymbolAddress((void**)&Woh, g_Woh);
    cudaGetSymbolAddress((void**)&Khi, g_Khi);
    cudaGetSymbolAddress((void**)&Klo, g_Klo);
    cudaGetSymbolAddress((void**)&Vh, g_Vh);
    cudaGetSymbolAddress((void**)&sc, g_sc);

    cudaFuncSetAttribute(gemm_mma, cudaFuncAttributeMaxDynamicSharedMemorySize, G_SMEM);
    cudaFuncSetAttribute(gemm_mma2, cudaFuncAttributeMaxDynamicSharedMemorySize, G2_SMEM);
    cudaFuncSetAttribute(flash_mma, cudaFuncAttributeMaxDynamicSharedMemorySize, F_SMEM);

    const int convBlocks = (SEQ * HID / 4) / 256;

    convert_hl<<<convBlocks, 256>>>(x, Ahi, Alo);
    transpose_all<<<dim3(160, HID / 32), 256>>>(q_proj, k_proj, v_proj, o_proj, Whi, Wlo, Woh);
    sc_init<<<SEQ * 32 / 256, 256>>>(inv_freq, sc);

    // fused QKV projection (bf16 3-pass), 64x128 tiles, occ 3
    gemm_mma<<<dim3(QKVN / 128, SEQ / 64), 256, G_SMEM>>>(Ahi, Alo, Whi, Wlo, QKVb,
                                                          SEQ, QKVN, HID);

    // RoPE + splits
    rope_conv<<<SEQ * NQH / 8, 256>>>(QKVb, Ahi, Alo, sc, NQH, 0.125f, QKVN, 0);
    rope_conv<<<SEQ * NKH / 8, 256>>>(QKVb, Khi, Klo, sc, NKH, 1.0f, QKVN, HID);
    convert_h16_strided<<<(SEQ * KVD / 4) / 256, 256>>>(QKVb, Vh, QKVN, HID + KVD, KVD);

    // flash attention (S bf16 3-pass, PV fp16 2-pass)
    flash_mma<<<dim3(SEQ / 128, NQH), 256, F_SMEM>>>(Ahi, Alo, Khi, Klo, Vh, Ohf, Olf);

    // out = O @ o_proj (fp16 2-pass)
    gemm_mma2<<<dim3(HID / 128, SEQ / 128), 256, G2_SMEM>>>(Ohf, Olf, Woh, out, SEQ, HID, HID);
}

// round 10
// speedup vs baseline: 1.0246x; 1.0246x over previous
#include <cuda_runtime.h>
#include <cuda_bf16.h>
#include <cuda_fp16.h>
#include <math.h>
#include <cstdint>

#define SEQ 2048
#define HID 2048
#define KVD 512
#define QKVN 3072
#define NQH 32
#define NKH 8

// ---------------- scratch (no allocations allowed) ----------------
__device__ float g_QKV[SEQ * QKVN];
__device__ __nv_bfloat16 g_Ahi[SEQ * HID];
__device__ __nv_bfloat16 g_Alo[SEQ * HID];
__device__ __half g_Ohf[SEQ * HID];
__device__ __half g_Olf[SEQ * HID];
__device__ __nv_bfloat16 g_Whi[QKVN * HID];   // transposed q|k|v weights [N,K] bf16
__device__ __nv_bfloat16 g_Wlo[QKVN * HID];
__device__ __half g_Woh[HID * HID];           // transposed o weights, fp16 hi only
__device__ __nv_bfloat16 g_Khi[SEQ * KVD];
__device__ __nv_bfloat16 g_Klo[SEQ * KVD];
__device__ __half g_Vh[SEQ * KVD];            // V fp16 hi only
__device__ float2 g_sc[SEQ * 32];             // sincos LUT

// ---------------- helpers ----------------
__device__ __forceinline__ uint32_t smem_u32(const void* p) {
    uint32_t a;
    asm("{ .reg .u64 t; cvta.to.shared.u64 t, %1; cvt.u32.u64 %0, t; }" : "=r"(a) : "l"(p));
    return a;
}

#define LDSM4(r0, r1, r2, r3, addr) \
    asm volatile("ldmatrix.sync.aligned.m8n8.x4.shared.b16 {%0,%1,%2,%3}, [%4];" \
        : "=r"(r0), "=r"(r1), "=r"(r2), "=r"(r3) : "r"(addr))

#define LDSM4T(r0, r1, r2, r3, addr) \
    asm volatile("ldmatrix.sync.aligned.m8n8.x4.trans.shared.b16 {%0,%1,%2,%3}, [%4];" \
        : "=r"(r0), "=r"(r1), "=r"(r2), "=r"(r3) : "r"(addr))

#define MMA16816(d, a, b0, b1) \
    asm volatile("mma.sync.aligned.m16n8k16.row.col.f32.bf16.bf16.f32 " \
        "{%0,%1,%2,%3},{%4,%5,%6,%7},{%8,%9},{%0,%1,%2,%3};" \
        : "+f"((d)[0]), "+f"((d)[1]), "+f"((d)[2]), "+f"((d)[3]) \
        : "r"((a)[0]), "r"((a)[1]), "r"((a)[2]), "r"((a)[3]), "r"(b0), "r"(b1))

#define MMA16816F(d, a, b0, b1) \
    asm volatile("mma.sync.aligned.m16n8k16.row.col.f32.f16.f16.f32 " \
        "{%0,%1,%2,%3},{%4,%5,%6,%7},{%8,%9},{%0,%1,%2,%3};" \
        : "+f"((d)[0]), "+f"((d)[1]), "+f"((d)[2]), "+f"((d)[3]) \
        : "r"((a)[0]), "r"((a)[1]), "r"((a)[2]), "r"((a)[3]), "r"(b0), "r"(b1))

#define CP_ASYNC16(dst, src) \
    asm volatile("cp.async.cg.shared.global [%0], [%1], 16;" :: "r"(dst), "l"(src))
#define CP_COMMIT() asm volatile("cp.async.commit_group;" ::: "memory")
#define CP_WAIT0()  asm volatile("cp.async.wait_group 0;" ::: "memory")
#define CP_WAIT1()  asm volatile("cp.async.wait_group 1;" ::: "memory")

// ---------------- elementwise kernels ----------------
__device__ __forceinline__ uint32_t pack_bf2(__nv_bfloat16 a, __nv_bfloat16 b) {
    __nv_bfloat162 t(a, b);
    return *reinterpret_cast<uint32_t*>(&t);
}

__global__ __launch_bounds__(256) void convert_hl(const float* __restrict__ X,
                                                  __nv_bfloat16* __restrict__ hi,
                                                  __nv_bfloat16* __restrict__ lo) {
    int i = blockIdx.x * 256 + threadIdx.x;
    float4 v = *(const float4*)(X + (size_t)i * 4);
    __nv_bfloat16 h0 = __float2bfloat16_rn(v.x), h1 = __float2bfloat16_rn(v.y);
    __nv_bfloat16 h2 = __float2bfloat16_rn(v.z), h3 = __float2bfloat16_rn(v.w);
    __nv_bfloat16 l0 = __float2bfloat16_rn(v.x - __bfloat162float(h0));
    __nv_bfloat16 l1 = __float2bfloat16_rn(v.y - __bfloat162float(h1));
    __nv_bfloat16 l2 = __float2bfloat16_rn(v.z - __bfloat162float(h2));
    __nv_bfloat16 l3 = __float2bfloat16_rn(v.w - __bfloat162float(h3));
    *(uint2*)(hi + (size_t)i * 4) = make_uint2(pack_bf2(h0, h1), pack_bf2(h2, h3));
    *(uint2*)(lo + (size_t)i * 4) = make_uint2(pack_bf2(l0, l1), pack_bf2(l2, l3));
}

// strided fp32 -> fp16 (hi only) for V
__global__ __launch_bounds__(256) void convert_h16_strided(const float* __restrict__ X,
                                                           __half* __restrict__ h,
                                                           int ld, int col0, int cols) {
    int i = blockIdx.x * 256 + threadIdx.x;
    int r = i / (cols / 4), q = i % (cols / 4);
    float4 v = *(const float4*)(X + (size_t)r * ld + col0 + q * 4);
    __half2 a = __floats2half2_rn(v.x, v.y);
    __half2 b = __floats2half2_rn(v.z, v.w);
    *(uint2*)(h + (size_t)r * cols + q * 4) =
        make_uint2(*reinterpret_cast<uint32_t*>(&a), *reinterpret_cast<uint32_t*>(&b));
}

// fused transpose: q,k,v -> bf16 hi/lo into Whi/Wlo; o -> fp16 hi into Woh
__global__ __launch_bounds__(256) void transpose_all(const float* __restrict__ Wq,
                                                     const float* __restrict__ Wk,
                                                     const float* __restrict__ Wv,
                                                     const float* __restrict__ Wo,
                                                     __nv_bfloat16* __restrict__ thi,
                                                     __nv_bfloat16* __restrict__ tlo,
                                                     __half* __restrict__ toh) {
    __shared__ float t[32][33];
    int bx = blockIdx.x;
    const float* W;
    int N, nblk, dstoff;
    bool is_o = false;
    if (bx < 64)       { W = Wq; N = HID; nblk = bx;      dstoff = 0; }
    else if (bx < 80)  { W = Wk; N = KVD; nblk = bx - 64; dstoff = HID; }
    else if (bx < 96)  { W = Wv; N = KVD; nblk = bx - 80; dstoff = HID + KVD; }
    else               { W = Wo; N = HID; nblk = bx - 96; dstoff = 0; is_o = true; }
    int tx = threadIdx.x & 31, ty = threadIdx.x >> 5;
    int k0 = blockIdx.y * 32, n0 = nblk * 32;
#pragma unroll
    for (int i = 0; i < 4; i++)
        t[ty + i * 8][tx] = W[(size_t)(k0 + ty + i * 8) * N + n0 + tx];
    __syncthreads();
#pragma unroll
    for (int i = 0; i < 4; i++) {
        float v = t[tx][ty + i * 8];
        size_t o = (size_t)(dstoff + n0 + ty + i * 8) * HID + k0 + tx;
        if (is_o) {
            toh[o] = __float2half_rn(v);
        } else {
            __nv_bfloat16 h = __float2bfloat16_rn(v);
            thi[o] = h;
            tlo[o] = __float2bfloat16_rn(v - __bfloat162float(h));
        }
    }
}

// sincos LUT init
__global__ __launch_bounds__(256) void sc_init(const float* __restrict__ inv_freq,
                                               float2* __restrict__ sc) {
    int i = blockIdx.x * 256 + threadIdx.x;
    int s = i >> 5, j = i & 31;
    float angle = (float)s * inv_freq[j];
    sc[i] = make_float2(sinf(angle), cosf(angle));
}

// RoPE + scale + bf16 hi/lo split, using LUT
__global__ __launch_bounds__(256) void rope_conv(const float* __restrict__ X,
                                                 __nv_bfloat16* __restrict__ hi,
                                                 __nv_bfloat16* __restrict__ lo,
                                                 const float2* __restrict__ sc,
                                                 int heads, float scale, int ld, int col0) {
    int idx = blockIdx.x * 8 + (threadIdx.x >> 5);
    int j = threadIdx.x & 31;
    int s = idx / heads;
    int h = idx - s * heads;
    const float* p = X + (size_t)s * ld + col0 + h * 64;
    float2 snc = sc[s * 32 + j];
    float a = p[j], b = p[32 + j];
    float r0 = (a * snc.y + b * snc.x) * scale;
    float r1 = (a * snc.x - b * snc.y) * scale;
    size_t o = (size_t)s * heads * 64 + h * 64;
    __nv_bfloat16 h0 = __float2bfloat16_rn(r0);
    __nv_bfloat16 h1 = __float2bfloat16_rn(r1);
    hi[o + j] = h0;
    hi[o + 32 + j] = h1;
    lo[o + j] = __float2bfloat16_rn(r0 - __bfloat162float(h0));
    lo[o + 32 + j] = __float2bfloat16_rn(r1 - __bfloat162float(h1));
}

// ---------------- bf16 3-pass GEMM (QKV): 128x128, occ 2, staggered LDSM ----------------
#define TILE_B 10240
#define BUF_B  40960
#define G_SMEM (2 * BUF_B)

// 128-row tile loader (2 ops/thread)
__device__ __forceinline__ void tile_async(uint32_t dst, const void* src_,
                                           int ldk, int tid) {
    const __nv_bfloat16* src = (const __nv_bfloat16*)src_;
#pragma unroll
    for (int t = 0; t < 2; t++) {
        int i = tid + t * 256;
        int r = i >> 2, q = i & 3;
        CP_ASYNC16(dst + r * 80 + q * 16, src + (size_t)r * ldk + q * 8);
    }
}

__global__ __launch_bounds__(256, 2) void gemm_mma(
    const __nv_bfloat16* __restrict__ Ahi, const __nv_bfloat16* __restrict__ Alo,
    const __nv_bfloat16* __restrict__ Bhi, const __nv_bfloat16* __restrict__ Blo,
    float* __restrict__ C, int M, int N, int K) {
    extern __shared__ char smem[];
    const uint32_t sb = smem_u32(smem);
    const int tid = threadIdx.x;
    const int w = tid >> 5;
    const int lane = tid & 31;
    const int wm = (w & 1) * 64;
    const int wn = (w >> 1) * 32;
    const int m0 = blockIdx.y * 128;
    const int n0 = blockIdx.x * 128;

    const int a_row = lane & 15;
    const int a_kh = (lane >> 4) & 1;
    const int b_n = (lane & 7) + ((lane >> 4) << 3);
    const int b_kh = (lane >> 3) & 1;

    float acc[4][4][4];
#pragma unroll
    for (int i = 0; i < 4; i++)
#pragma unroll
        for (int j = 0; j < 4; j++)
#pragma unroll
            for (int r = 0; r < 4; r++) acc[i][j][r] = 0.f;

    const int NC = K >> 5;
    {
        const size_t ak = (size_t)m0 * K;
        const size_t bk = (size_t)n0 * K;
        tile_async(sb,              Ahi + ak, K, tid);
        tile_async(sb + TILE_B,     Alo + ak, K, tid);
        tile_async(sb + 2 * TILE_B, Bhi + bk, K, tid);
        tile_async(sb + 3 * TILE_B, Blo + bk, K, tid);
        CP_COMMIT();
    }

    for (int c = 0; c < NC; c++) {
        CP_WAIT0();
        __syncthreads();
        if (c + 1 < NC) {
            const uint32_t nb = sb + ((c + 1) & 1) * BUF_B;
            const size_t ak = (size_t)m0 * K + (size_t)(c + 1) * 32;
            const size_t bk = (size_t)n0 * K + (size_t)(c + 1) * 32;
            tile_async(nb,              Ahi + ak, K, tid);
            tile_async(nb + TILE_B,     Alo + ak, K, tid);
            tile_async(nb + 2 * TILE_B, Bhi + bk, K, tid);
            tile_async(nb + 3 * TILE_B, Blo + bk, K, tid);
            CP_COMMIT();
        }
        const uint32_t base = sb + (c & 1) * BUF_B;

#pragma unroll
        for (int ks = 0; ks < 32; ks += 16) {
            const uint32_t aoff = (uint32_t)((wm + a_row) * 80 + (ks + a_kh * 8) * 2);
            const uint32_t boff = (uint32_t)((wn + b_n) * 80 + (ks + b_kh * 8) * 2);

            // stage 1: load ah + bh, run hi*hi while next loads can issue after
            uint32_t ah[4][4], bh[2][4];
#pragma unroll
            for (int mt = 0; mt < 4; mt++)
                LDSM4(ah[mt][0], ah[mt][1], ah[mt][2], ah[mt][3],
                      base + aoff + mt * 16 * 80);
#pragma unroll
            for (int np = 0; np < 2; np++)
                LDSM4(bh[np][0], bh[np][1], bh[np][2], bh[np][3],
                      base + 2 * TILE_B + boff + np * 16 * 80);
#pragma unroll
            for (int mt = 0; mt < 4; mt++)
#pragma unroll
                for (int np = 0; np < 2; np++) {
                    MMA16816(acc[mt][np * 2 + 0], ah[mt], bh[np][0], bh[np][1]);
                    MMA16816(acc[mt][np * 2 + 1], ah[mt], bh[np][2], bh[np][3]);
                }

            // stage 2: load bl (overlaps hi*hi drain), run hi*lo
            uint32_t bl[2][4];
#pragma unroll
            for (int np = 0; np < 2; np++)
                LDSM4(bl[np][0], bl[np][1], bl[np][2], bl[np][3],
                      base + 3 * TILE_B + boff + np * 16 * 80);
#pragma unroll
            for (int mt = 0; mt < 4; mt++)
#pragma unroll
                for (int np = 0; np < 2; np++) {
                    MMA16816(acc[mt][np * 2 + 0], ah[mt], bl[np][0], bl[np][1]);
                    MMA16816(acc[mt][np * 2 + 1], ah[mt], bl[np][2], bl[np][3]);
                }

            // stage 3: load al (overlaps hi*lo drain), run lo*hi
            uint32_t al[4][4];
#pragma unroll
            for (int mt = 0; mt < 4; mt++)
                LDSM4(al[mt][0], al[mt][1], al[mt][2], al[mt][3],
                      base + TILE_B + aoff + mt * 16 * 80);
#pragma unroll
            for (int mt = 0; mt < 4; mt++)
#pragma unroll
                for (int np = 0; np < 2; np++) {
                    MMA16816(acc[mt][np * 2 + 0], al[mt], bh[np][0], bh[np][1]);
                    MMA16816(acc[mt][np * 2 + 1], al[mt], bh[np][2], bh[np][3]);
                }
        }
    }

    const int g = lane >> 2, c2 = lane & 3;
#pragma unroll
    for (int mt = 0; mt < 4; mt++) {
        const int row = m0 + wm + mt * 16 + g;
#pragma unroll
        for (int nt = 0; nt < 4; nt++) {
            const int col = n0 + wn + nt * 8 + c2 * 2;
            *(float2*)&C[(size_t)row * N + col] =
                make_float2(acc[mt][nt][0], acc[mt][nt][1]);
            *(float2*)&C[(size_t)(row + 8) * N + col] =
                make_float2(acc[mt][nt][2], acc[mt][nt][3]);
        }
    }
}

// ---------------- fp16 2-pass GEMM (O projection), occ 2, staggered ----------------
#define BUF2_B 30720
#define G2_SMEM (2 * BUF2_B)

__global__ __launch_bounds__(256, 2) void gemm_mma2(
    const __half* __restrict__ Ahi, const __half* __restrict__ Alo,
    const __half* __restrict__ Bh,
    float* __restrict__ C, int M, int N, int K) {
    extern __shared__ char smem[];
    const uint32_t sb = smem_u32(smem);
    const int tid = threadIdx.x;
    const int w = tid >> 5;
    const int lane = tid & 31;
    const int wm = (w & 1) * 64;
    const int wn = (w >> 1) * 32;
    const int m0 = blockIdx.y * 128;
    const int n0 = blockIdx.x * 128;

    const int a_row = lane & 15;
    const int a_kh = (lane >> 4) & 1;
    const int b_n = (lane & 7) + ((lane >> 4) << 3);
    const int b_kh = (lane >> 3) & 1;

    float acc[4][4][4];
#pragma unroll
    for (int i = 0; i < 4; i++)
#pragma unroll
        for (int j = 0; j < 4; j++)
#pragma unroll
            for (int r = 0; r < 4; r++) acc[i][j][r] = 0.f;

    const int NC = K >> 5;
    {
        const size_t ak = (size_t)m0 * K;
        const size_t bk = (size_t)n0 * K;
        tile_async(sb,              Ahi + ak, K, tid);
        tile_async(sb + TILE_B,     Alo + ak, K, tid);
        tile_async(sb + 2 * TILE_B, Bh + bk, K, tid);
        CP_COMMIT();
    }

    for (int c = 0; c < NC; c++) {
        CP_WAIT0();
        __syncthreads();
        if (c + 1 < NC) {
            const uint32_t nb = sb + ((c + 1) & 1) * BUF2_B;
            const size_t ak = (size_t)m0 * K + (size_t)(c + 1) * 32;
            const size_t bk = (size_t)n0 * K + (size_t)(c + 1) * 32;
            tile_async(nb,              Ahi + ak, K, tid);
            tile_async(nb + TILE_B,     Alo + ak, K, tid);
            tile_async(nb + 2 * TILE_B, Bh + bk, K, tid);
            CP_COMMIT();
        }
        const uint32_t base = sb + (c & 1) * BUF2_B;

#pragma unroll
        for (int ks = 0; ks < 32; ks += 16) {
            const uint32_t aoff = (uint32_t)((wm + a_row) * 80 + (ks + a_kh * 8) * 2);
            const uint32_t boff = (uint32_t)((wn + b_n) * 80 + (ks + b_kh * 8) * 2);

            uint32_t ah[4][4], bh[2][4];
#pragma unroll
            for (int mt = 0; mt < 4; mt++)
                LDSM4(ah[mt][0], ah[mt][1], ah[mt][2], ah[mt][3],
                      base + aoff + mt * 16 * 80);
#pragma unroll
            for (int np = 0; np < 2; np++)
                LDSM4(bh[np][0], bh[np][1], bh[np][2], bh[np][3],
                      base + 2 * TILE_B + boff + np * 16 * 80);
#pragma unroll
            for (int mt = 0; mt < 4; mt++)
#pragma unroll
                for (int np = 0; np < 2; np++) {
                    MMA16816F(acc[mt][np * 2 + 0], ah[mt], bh[np][0], bh[np][1]);
                    MMA16816F(acc[mt][np * 2 + 1], ah[mt], bh[np][2], bh[np][3]);
                }

            uint32_t al[4][4];
#pragma unroll
            for (int mt = 0; mt < 4; mt++)
                LDSM4(al[mt][0], al[mt][1], al[mt][2], al[mt][3],
                      base + TILE_B + aoff + mt * 16 * 80);
#pragma unroll
            for (int mt = 0; mt < 4; mt++)
#pragma unroll
                for (int np = 0; np < 2; np++) {
                    MMA16816F(acc[mt][np * 2 + 0], al[mt], bh[np][0], bh[np][1]);
                    MMA16816F(acc[mt][np * 2 + 1], al[mt], bh[np][2], bh[np][3]);
                }
        }
    }

    const int g = lane >> 2, c2 = lane & 3;
#pragma unroll
    for (int mt = 0; mt < 4; mt++) {
        const int row = m0 + wm + mt * 16 + g;
#pragma unroll
        for (int nt = 0; nt < 4; nt++) {
            const int col = n0 + wn + nt * 8 + c2 * 2;
            *(float2*)&C[(size_t)row * N + col] =
                make_float2(acc[mt][nt][0], acc[mt][nt][1]);
            *(float2*)&C[(size_t)(row + 8) * N + col] =
                make_float2(acc[mt][nt][2], acc[mt][nt][3]);
        }
    }
}

// ---------------- tensor-core flash attention (unchanged from R8) ----------------
#define FQ_H 0
#define FQ_L 18432
#define FKV  36864
#define FKV_STRIDE 27648
#define F_SMEM 92160

__device__ __forceinline__ void pack_hl16(float p0, float p1, uint32_t& hi, uint32_t& lo) {
    __half2 h = __floats2half2_rn(p0, p1);
    hi = *reinterpret_cast<uint32_t*>(&h);
    __half2 l = __floats2half2_rn(p0 - __half2float(__low2half(h)),
                                  p1 - __half2float(__high2half(h)));
    lo = *reinterpret_cast<uint32_t*>(&l);
}

__global__ __launch_bounds__(256, 2) void flash_mma(
    const __nv_bfloat16* __restrict__ Qhi, const __nv_bfloat16* __restrict__ Qlo,
    const __nv_bfloat16* __restrict__ Khi, const __nv_bfloat16* __restrict__ Klo,
    const __half* __restrict__ Vh,
    __half* __restrict__ Ohf, __half* __restrict__ Olf) {
    extern __shared__ char smem[];
    const uint32_t sb = smem_u32(smem);
    const int tid = threadIdx.x;
    const int lane = tid & 31;
    const int w = tid >> 5;
    const int ib = gridDim.x - 1 - blockIdx.x;
    const int qh = blockIdx.y;
    const int kh = qh >> 2;
    const int qbase = ib * 128;

#pragma unroll
    for (int i = 0; i < 8; i++) {
        int idx = tid + i * 256;
        int sub = idx >> 10, r = (idx >> 3) & 127, q = idx & 7;
        const __nv_bfloat16* src = (sub ? Qlo : Qhi) + (size_t)(qbase + r) * HID + qh * 64 + q * 8;
        CP_ASYNC16(sb + sub * 18432 + r * 144 + q * 16, src);
    }
    CP_COMMIT();

#pragma unroll
    for (int i = 0; i < 6; i++) {
        int idx = tid + i * 256;
        int sub = idx >> 9, r = (idx >> 3) & 63, q = idx & 7;
        const uint16_t* base = (sub == 0) ? (const uint16_t*)Khi
                               : (sub == 1) ? (const uint16_t*)Klo : (const uint16_t*)Vh;
        const void* src = base + (size_t)r * KVD + kh * 64 + q * 8;
        CP_ASYNC16(sb + FKV + sub * 9216 + r * 144 + q * 16, src);
    }
    CP_COMMIT();

    const int a_row = lane & 15, a_kh = lane >> 4;
    const int b_n = (lane & 7) + ((lane >> 4) << 3), b_kh = (lane >> 3) & 1;
    const int v_k = (lane & 7) + ((lane >> 3) & 1) * 8, v_n = (lane >> 4) * 8;
    const int g = lane >> 2, tg = lane & 3;

    float o[8][4];
#pragma unroll
    for (int nt = 0; nt < 8; nt++)
#pragma unroll
        for (int r = 0; r < 4; r++) o[nt][r] = 0.f;
    float m0 = -1e30f, m1 = -1e30f, l0 = 0.f, l1 = 0.f;

    const int jbmax = 2 * ib + 1;
    for (int jb = 0; jb <= jbmax; jb++) {
        const uint32_t kvb = sb + FKV + (jb & 1) * FKV_STRIDE;
        __syncthreads();
        if (jb < jbmax) {
            const uint32_t nb = sb + FKV + ((jb + 1) & 1) * FKV_STRIDE;
#pragma unroll
            for (int i = 0; i < 6; i++) {
                int idx = tid + i * 256;
                int sub = idx >> 9, r = (idx >> 3) & 63, q = idx & 7;
                const uint16_t* base = (sub == 0) ? (const uint16_t*)Khi
                                       : (sub == 1) ? (const uint16_t*)Klo : (const uint16_t*)Vh;
                const void* src = base + (size_t)((jb + 1) * 64 + r) * KVD + kh * 64 + q * 8;
                CP_ASYNC16(nb + sub * 9216 + r * 144 + q * 16, src);
            }
            CP_COMMIT();
            CP_WAIT1();
        } else {
            CP_WAIT0();
        }
        __syncthreads();

        // S = Q K^T (bf16 3-pass, pass-major)
        float s[8][4];
#pragma unroll
        for (int nt = 0; nt < 8; nt++)
#pragma unroll
            for (int r = 0; r < 4; r++) s[nt][r] = 0.f;
#pragma unroll
        for (int kc = 0; kc < 4; kc++) {
            uint32_t ah[4], al[4];
            const uint32_t aoff = (w * 16 + a_row) * 144 + (kc * 16 + a_kh * 8) * 2;
            LDSM4(ah[0], ah[1], ah[2], ah[3], sb + FQ_H + aoff);
            LDSM4(al[0], al[1], al[2], al[3], sb + FQ_L + aoff);
#pragma unroll
            for (int n2p = 0; n2p < 2; n2p++) {
                uint32_t bh[2][4], bl[2][4];
#pragma unroll
                for (int j = 0; j < 2; j++) {
                    const int n2 = n2p * 2 + j;
                    const uint32_t boff = (n2 * 16 + b_n) * 144 + (kc * 16 + b_kh * 8) * 2;
                    LDSM4(bh[j][0], bh[j][1], bh[j][2], bh[j][3], kvb + boff);
                    LDSM4(bl[j][0], bl[j][1], bl[j][2], bl[j][3], kvb + 9216 + boff);
                }
#pragma unroll
                for (int j = 0; j < 2; j++) {
                    const int n2 = n2p * 2 + j;
                    MMA16816(s[n2 * 2 + 0], ah, bh[j][0], bh[j][1]);
                    MMA16816(s[n2 * 2 + 1], ah, bh[j][2], bh[j][3]);
                }
#pragma unroll
                for (int j = 0; j < 2; j++) {
                    const int n2 = n2p * 2 + j;
                    MMA16816(s[n2 * 2 + 0], ah, bl[j][0], bl[j][1]);
                    MMA16816(s[n2 * 2 + 1], ah, bl[j][2], bl[j][3]);
                }
#pragma unroll
                for (int j = 0; j < 2; j++) {
                    const int n2 = n2p * 2 + j;
                    MMA16816(s[n2 * 2 + 0], al, bh[j][0], bh[j][1]);
                    MMA16816(s[n2 * 2 + 1], al, bh[j][2], bh[j][3]);
                }
            }
        }

        if (jb >= 2 * ib) {
            const int row0 = qbase + w * 16 + g;
            const int row1 = row0 + 8;
#pragma unroll
            for (int nt = 0; nt < 8; nt++) {
                const int col = jb * 64 + nt * 8 + tg * 2;
                if (col > row0) s[nt][0] = -1e30f;
                if (col + 1 > row0) s[nt][1] = -1e30f;
                if (col > row1) s[nt][2] = -1e30f;
                if (col + 1 > row1) s[nt][3] = -1e30f;
            }
        }

        float mx0 = -1e30f, mx1 = -1e30f;
#pragma unroll
        for (int nt = 0; nt < 8; nt++) {
            mx0 = fmaxf(mx0, fmaxf(s[nt][0], s[nt][1]));
            mx1 = fmaxf(mx1, fmaxf(s[nt][2], s[nt][3]));
        }
        mx0 = fmaxf(mx0, __shfl_xor_sync(0xffffffff, mx0, 1));
        mx0 = fmaxf(mx0, __shfl_xor_sync(0xffffffff, mx0, 2));
        mx1 = fmaxf(mx1, __shfl_xor_sync(0xffffffff, mx1, 1));
        mx1 = fmaxf(mx1, __shfl_xor_sync(0xffffffff, mx1, 2));
        const float mn0 = fmaxf(m0, mx0), mn1 = fmaxf(m1, mx1);
        const float al0 = __expf(m0 - mn0), al1 = __expf(m1 - mn1);
        m0 = mn0; m1 = mn1;

        float rs0 = 0.f, rs1 = 0.f;
#pragma unroll
        for (int nt = 0; nt < 8; nt++) {
            s[nt][0] = __expf(s[nt][0] - mn0);
            s[nt][1] = __expf(s[nt][1] - mn0);
            s[nt][2] = __expf(s[nt][2] - mn1);
            s[nt][3] = __expf(s[nt][3] - mn1);
            rs0 += s[nt][0] + s[nt][1];
            rs1 += s[nt][2] + s[nt][3];
            o[nt][0] *= al0; o[nt][1] *= al0;
            o[nt][2] *= al1; o[nt][3] *= al1;
        }
        rs0 += __shfl_xor_sync(0xffffffff, rs0, 1);
        rs0 += __shfl_xor_sync(0xffffffff, rs0, 2);
        rs1 += __shfl_xor_sync(0xffffffff, rs1, 1);
        rs1 += __shfl_xor_sync(0xffffffff, rs1, 2);
        l0 = l0 * al0 + rs0;
        l1 = l1 * al1 + rs1;

        // O += P @ V : fp16 2-pass
#pragma unroll
        for (int kc2 = 0; kc2 < 4; kc2++) {
            uint32_t aph[4], apl[4];
            pack_hl16(s[2 * kc2][0], s[2 * kc2][1], aph[0], apl[0]);
            pack_hl16(s[2 * kc2][2], s[2 * kc2][3], aph[1], apl[1]);
            pack_hl16(s[2 * kc2 + 1][0], s[2 * kc2 + 1][1], aph[2], apl[2]);
            pack_hl16(s[2 * kc2 + 1][2], s[2 * kc2 + 1][3], aph[3], apl[3]);
#pragma unroll
            for (int n2p = 0; n2p < 2; n2p++) {
                uint32_t vh[2][4];
#pragma unroll
                for (int j = 0; j < 2; j++) {
                    const int n2 = n2p * 2 + j;
                    const uint32_t voff = (kc2 * 16 + v_k) * 144 + (n2 * 16 + v_n) * 2;
                    LDSM4T(vh[j][0], vh[j][1], vh[j][2], vh[j][3], kvb + 2 * 9216 + voff);
                }
#pragma unroll
                for (int j = 0; j < 2; j++) {
                    const int n2 = n2p * 2 + j;
                    MMA16816F(o[n2 * 2 + 0], aph, vh[j][0], vh[j][1]);
                    MMA16816F(o[n2 * 2 + 1], aph, vh[j][2], vh[j][3]);
                }
#pragma unroll
                for (int j = 0; j < 2; j++) {
                    const int n2 = n2p * 2 + j;
                    MMA16816F(o[n2 * 2 + 0], apl, vh[j][0], vh[j][1]);
                    MMA16816F(o[n2 * 2 + 1], apl, vh[j][2], vh[j][3]);
                }
            }
        }
    }

    const float il0 = 1.0f / l0, il1 = 1.0f / l1;
    const int row0 = qbase + w * 16 + g;
#pragma unroll
    for (int nt = 0; nt < 8; nt++) {
        const int col = qh * 64 + nt * 8 + tg * 2;
        uint32_t h, l;
        pack_hl16(o[nt][0] * il0, o[nt][1] * il0, h, l);
        *(uint32_t*)&Ohf[(size_t)row0 * HID + col] = h;
        *(uint32_t*)&Olf[(size_t)row0 * HID + col] = l;
        pack_hl16(o[nt][2] * il1, o[nt][3] * il1, h, l);
        *(uint32_t*)&Ohf[(size_t)(row0 + 8) * HID + col] = h;
        *(uint32_t*)&Olf[(size_t)(row0 + 8) * HID + col] = l;
    }
}

// ---------------------------------------------------------------------------
extern "C" void kernel_launch(void* const* d_in, const int* in_sizes, int n_in,
                              void* d_out, int out_size) {
    const float* x        = (const float*)d_in[0];
    const float* q_proj   = (const float*)d_in[1];
    const float* k_proj   = (const float*)d_in[2];
    const float* v_proj   = (const float*)d_in[3];
    const float* o_proj   = (const float*)d_in[4];
    const float* inv_freq = (const float*)d_in[5];
    float* out = (float*)d_out;

    float *QKVb;
    __nv_bfloat16 *Ahi, *Alo, *Whi, *Wlo, *Khi, *Klo;
    __half *Ohf, *Olf, *Woh, *Vh;
    float2* sc;
    cudaGetSymbolAddress((void**)&QKVb, g_QKV);
    cudaGetSymbolAddress((void**)&Ahi, g_Ahi);
    cudaGetSymbolAddress((void**)&Alo, g_Alo);
    cudaGetSymbolAddress((void**)&Ohf, g_Ohf);
    cudaGetSymbolAddress((void**)&Olf, g_Olf);
    cudaGetSymbolAddress((void**)&Whi, g_Whi);
    cudaGetSymbolAddress((void**)&Wlo, g_Wlo);
    cudaGetSymbolAddress((void**)&Woh, g_Woh);
    cudaGetSymbolAddress((void**)&Khi, g_Khi);
    cudaGetSymbolAddress((void**)&Klo, g_Klo);
    cudaGetSymbolAddress((void**)&Vh, g_Vh);
    cudaGetSymbolAddress((void**)&sc, g_sc);

    cudaFuncSetAttribute(gemm_mma, cudaFuncAttributeMaxDynamicSharedMemorySize, G_SMEM);
    cudaFuncSetAttribute(gemm_mma2, cudaFuncAttributeMaxDynamicSharedMemorySize, G2_SMEM);
    cudaFuncSetAttribute(flash_mma, cudaFuncAttributeMaxDynamicSharedMemorySize, F_SMEM);

    const int convBlocks = (SEQ * HID / 4) / 256;

    convert_hl<<<convBlocks, 256>>>(x, Ahi, Alo);
    transpose_all<<<dim3(160, HID / 32), 256>>>(q_proj, k_proj, v_proj, o_proj, Whi, Wlo, Woh);
    sc_init<<<SEQ * 32 / 256, 256>>>(inv_freq, sc);

    // fused QKV projection (bf16 3-pass), 128x128 occ 2, staggered LDSM
    gemm_mma<<<dim3(QKVN / 128, SEQ / 128), 256, G_SMEM>>>(Ahi, Alo, Whi, Wlo, QKVb,
                                                           SEQ, QKVN, HID);

    // RoPE + splits
    rope_conv<<<SEQ * NQH / 8, 256>>>(QKVb, Ahi, Alo, sc, NQH, 0.125f, QKVN, 0);
    rope_conv<<<SEQ * NKH / 8, 256>>>(QKVb, Khi, Klo, sc, NKH, 1.0f, QKVN, HID);
    convert_h16_strided<<<(SEQ * KVD / 4) / 256, 256>>>(QKVb, Vh, QKVN, HID + KVD, KVD);

    // flash attention (S bf16 3-pass, PV fp16 2-pass)
    flash_mma<<<dim3(SEQ / 128, NQH), 256, F_SMEM>>>(Ahi, Alo, Khi, Klo, Vh, Ohf, Olf);

    // out = O @ o_proj (fp16 2-pass)
    gemm_mma2<<<dim3(HID / 128, SEQ / 128), 256, G2_SMEM>>>(Ohf, Olf, Woh, out, SEQ, HID, HID);
}

// round 11
// speedup vs baseline: 1.1771x; 1.1488x over previous
#include <cuda_runtime.h>
#include <cuda_bf16.h>
#include <cuda_fp16.h>
#include <math.h>
#include <cstdint>

#define SEQ 2048
#define HID 2048
#define KVD 512
#define QKVN 3072
#define WROWS 5120
#define NQH 32
#define NKH 8

// ---------------- scratch (no allocations allowed) ----------------
__device__ float g_QKV[SEQ * QKVN];
__device__ __half g_Axh[SEQ * HID];          // x fp16 hi
__device__ __half g_Axl[SEQ * HID];          // x fp16 lo
__device__ __half g_Ohf[SEQ * HID];
__device__ __half g_Olf[SEQ * HID];
__device__ __half g_Wh[WROWS * HID];         // transposed q|k|v|o weights, fp16 hi
__device__ __nv_bfloat16 g_Khi[SEQ * KVD];
__device__ __nv_bfloat16 g_Klo[SEQ * KVD];
__device__ __half g_Vh[SEQ * KVD];           // V fp16 hi only
__device__ float2 g_sc[SEQ * 32];            // sincos LUT

// ---------------- helpers ----------------
__device__ __forceinline__ uint32_t smem_u32(const void* p) {
    uint32_t a;
    asm("{ .reg .u64 t; cvta.to.shared.u64 t, %1; cvt.u32.u64 %0, t; }" : "=r"(a) : "l"(p));
    return a;
}

#define LDSM4(r0, r1, r2, r3, addr) \
    asm volatile("ldmatrix.sync.aligned.m8n8.x4.shared.b16 {%0,%1,%2,%3}, [%4];" \
        : "=r"(r0), "=r"(r1), "=r"(r2), "=r"(r3) : "r"(addr))

#define LDSM4T(r0, r1, r2, r3, addr) \
    asm volatile("ldmatrix.sync.aligned.m8n8.x4.trans.shared.b16 {%0,%1,%2,%3}, [%4];" \
        : "=r"(r0), "=r"(r1), "=r"(r2), "=r"(r3) : "r"(addr))

#define MMA16816(d, a, b0, b1) \
    asm volatile("mma.sync.aligned.m16n8k16.row.col.f32.bf16.bf16.f32 " \
        "{%0,%1,%2,%3},{%4,%5,%6,%7},{%8,%9},{%0,%1,%2,%3};" \
        : "+f"((d)[0]), "+f"((d)[1]), "+f"((d)[2]), "+f"((d)[3]) \
        : "r"((a)[0]), "r"((a)[1]), "r"((a)[2]), "r"((a)[3]), "r"(b0), "r"(b1))

#define MMA16816F(d, a, b0, b1) \
    asm volatile("mma.sync.aligned.m16n8k16.row.col.f32.f16.f16.f32 " \
        "{%0,%1,%2,%3},{%4,%5,%6,%7},{%8,%9},{%0,%1,%2,%3};" \
        : "+f"((d)[0]), "+f"((d)[1]), "+f"((d)[2]), "+f"((d)[3]) \
        : "r"((a)[0]), "r"((a)[1]), "r"((a)[2]), "r"((a)[3]), "r"(b0), "r"(b1))

#define CP_ASYNC16(dst, src) \
    asm volatile("cp.async.cg.shared.global [%0], [%1], 16;" :: "r"(dst), "l"(src))
#define CP_COMMIT() asm volatile("cp.async.commit_group;" ::: "memory")
#define CP_WAIT0()  asm volatile("cp.async.wait_group 0;" ::: "memory")
#define CP_WAIT1()  asm volatile("cp.async.wait_group 1;" ::: "memory")

// ---------------- elementwise kernels ----------------
__device__ __forceinline__ void pack_hl16(float p0, float p1, uint32_t& hi, uint32_t& lo) {
    __half2 h = __floats2half2_rn(p0, p1);
    hi = *reinterpret_cast<uint32_t*>(&h);
    __half2 l = __floats2half2_rn(p0 - __half2float(__low2half(h)),
                                  p1 - __half2float(__high2half(h)));
    lo = *reinterpret_cast<uint32_t*>(&l);
}

// fp32 -> fp16 hi/lo
__global__ __launch_bounds__(256) void convert_hl16(const float* __restrict__ X,
                                                    __half* __restrict__ hi,
                                                    __half* __restrict__ lo) {
    int i = blockIdx.x * 256 + threadIdx.x;
    float4 v = *(const float4*)(X + (size_t)i * 4);
    uint32_t h0, l0, h1, l1;
    pack_hl16(v.x, v.y, h0, l0);
    pack_hl16(v.z, v.w, h1, l1);
    *(uint2*)(hi + (size_t)i * 4) = make_uint2(h0, h1);
    *(uint2*)(lo + (size_t)i * 4) = make_uint2(l0, l1);
}

// strided fp32 -> fp16 (hi only) for V
__global__ __launch_bounds__(256) void convert_h16_strided(const float* __restrict__ X,
                                                           __half* __restrict__ h,
                                                           int ld, int col0, int cols) {
    int i = blockIdx.x * 256 + threadIdx.x;
    int r = i / (cols / 4), q = i % (cols / 4);
    float4 v = *(const float4*)(X + (size_t)r * ld + col0 + q * 4);
    __half2 a = __floats2half2_rn(v.x, v.y);
    __half2 b = __floats2half2_rn(v.z, v.w);
    *(uint2*)(h + (size_t)r * cols + q * 4) =
        make_uint2(*reinterpret_cast<uint32_t*>(&a), *reinterpret_cast<uint32_t*>(&b));
}

// fused transpose: all 4 weight matrices -> fp16 hi into Wh [WROWS, HID]
__global__ __launch_bounds__(256) void transpose_all16(const float* __restrict__ Wq,
                                                       const float* __restrict__ Wk,
                                                       const float* __restrict__ Wv,
                                                       const float* __restrict__ Wo,
                                                       __half* __restrict__ toh) {
    __shared__ float t[32][33];
    int bx = blockIdx.x;
    const float* W;
    int N, nblk, dstoff;
    if (bx < 64)       { W = Wq; N = HID; nblk = bx;      dstoff = 0; }
    else if (bx < 80)  { W = Wk; N = KVD; nblk = bx - 64; dstoff = HID; }
    else if (bx < 96)  { W = Wv; N = KVD; nblk = bx - 80; dstoff = HID + KVD; }
    else               { W = Wo; N = HID; nblk = bx - 96; dstoff = QKVN; }
    int tx = threadIdx.x & 31, ty = threadIdx.x >> 5;
    int k0 = blockIdx.y * 32, n0 = nblk * 32;
#pragma unroll
    for (int i = 0; i < 4; i++)
        t[ty + i * 8][tx] = W[(size_t)(k0 + ty + i * 8) * N + n0 + tx];
    __syncthreads();
#pragma unroll
    for (int i = 0; i < 4; i++) {
        float v = t[tx][ty + i * 8];
        toh[(size_t)(dstoff + n0 + ty + i * 8) * HID + k0 + tx] = __float2half_rn(v);
    }
}

// sincos LUT init
__global__ __launch_bounds__(256) void sc_init(const float* __restrict__ inv_freq,
                                               float2* __restrict__ sc) {
    int i = blockIdx.x * 256 + threadIdx.x;
    int s = i >> 5, j = i & 31;
    float angle = (float)s * inv_freq[j];
    sc[i] = make_float2(sinf(angle), cosf(angle));
}

// RoPE + scale + bf16 hi/lo split, using LUT
__device__ __forceinline__ uint32_t pack_bf2(__nv_bfloat16 a, __nv_bfloat16 b) {
    __nv_bfloat162 t(a, b);
    return *reinterpret_cast<uint32_t*>(&t);
}
__global__ __launch_bounds__(256) void rope_conv(const float* __restrict__ X,
                                                 __nv_bfloat16* __restrict__ hi,
                                                 __nv_bfloat16* __restrict__ lo,
                                                 const float2* __restrict__ sc,
                                                 int heads, float scale, int ld, int col0) {
    int idx = blockIdx.x * 8 + (threadIdx.x >> 5);
    int j = threadIdx.x & 31;
    int s = idx / heads;
    int h = idx - s * heads;
    const float* p = X + (size_t)s * ld + col0 + h * 64;
    float2 snc = sc[s * 32 + j];
    float a = p[j], b = p[32 + j];
    float r0 = (a * snc.y + b * snc.x) * scale;
    float r1 = (a * snc.x - b * snc.y) * scale;
    size_t o = (size_t)s * heads * 64 + h * 64;
    __nv_bfloat16 h0 = __float2bfloat16_rn(r0);
    __nv_bfloat16 h1 = __float2bfloat16_rn(r1);
    hi[o + j] = h0;
    hi[o + 32 + j] = h1;
    lo[o + j] = __float2bfloat16_rn(r0 - __bfloat162float(h0));
    lo[o + 32 + j] = __float2bfloat16_rn(r1 - __bfloat162float(h1));
}

// ---------------- fp16 2-pass GEMM (QKV + O projection), 128x128 occ 2 ----------------
#define TILE_B 10240
#define BUF2_B 30720
#define G2_SMEM (2 * BUF2_B)

// 128-row tile loader (2 ops/thread)
__device__ __forceinline__ void tile_async(uint32_t dst, const void* src_,
                                           int ldk, int tid) {
    const __half* src = (const __half*)src_;
#pragma unroll
    for (int t = 0; t < 2; t++) {
        int i = tid + t * 256;
        int r = i >> 2, q = i & 3;
        CP_ASYNC16(dst + r * 80 + q * 16, src + (size_t)r * ldk + q * 8);
    }
}

__global__ __launch_bounds__(256, 2) void gemm_mma2(
    const __half* __restrict__ Ahi, const __half* __restrict__ Alo,
    const __half* __restrict__ Bh,
    float* __restrict__ C, int M, int N, int K) {
    extern __shared__ char smem[];
    const uint32_t sb = smem_u32(smem);
    const int tid = threadIdx.x;
    const int w = tid >> 5;
    const int lane = tid & 31;
    const int wm = (w & 1) * 64;
    const int wn = (w >> 1) * 32;
    const int m0 = blockIdx.y * 128;
    const int n0 = blockIdx.x * 128;

    const int a_row = lane & 15;
    const int a_kh = (lane >> 4) & 1;
    const int b_n = (lane & 7) + ((lane >> 4) << 3);
    const int b_kh = (lane >> 3) & 1;

    float acc[4][4][4];
#pragma unroll
    for (int i = 0; i < 4; i++)
#pragma unroll
        for (int j = 0; j < 4; j++)
#pragma unroll
            for (int r = 0; r < 4; r++) acc[i][j][r] = 0.f;

    const int NC = K >> 5;
    {
        const size_t ak = (size_t)m0 * K;
        const size_t bk = (size_t)n0 * K;
        tile_async(sb,              Ahi + ak, K, tid);
        tile_async(sb + TILE_B,     Alo + ak, K, tid);
        tile_async(sb + 2 * TILE_B, Bh + bk, K, tid);
        CP_COMMIT();
    }

    for (int c = 0; c < NC; c++) {
        CP_WAIT0();
        __syncthreads();
        if (c + 1 < NC) {
            const uint32_t nb = sb + ((c + 1) & 1) * BUF2_B;
            const size_t ak = (size_t)m0 * K + (size_t)(c + 1) * 32;
            const size_t bk = (size_t)n0 * K + (size_t)(c + 1) * 32;
            tile_async(nb,              Ahi + ak, K, tid);
            tile_async(nb + TILE_B,     Alo + ak, K, tid);
            tile_async(nb + 2 * TILE_B, Bh + bk, K, tid);
            CP_COMMIT();
        }
        const uint32_t base = sb + (c & 1) * BUF2_B;

#pragma unroll
        for (int ks = 0; ks < 32; ks += 16) {
            uint32_t ah[4][4], al[4][4], bh[2][4];
            const uint32_t aoff = (uint32_t)((wm + a_row) * 80 + (ks + a_kh * 8) * 2);
            const uint32_t boff = (uint32_t)((wn + b_n) * 80 + (ks + b_kh * 8) * 2);
#pragma unroll
            for (int mt = 0; mt < 4; mt++) {
                LDSM4(ah[mt][0], ah[mt][1], ah[mt][2], ah[mt][3],
                      base + aoff + mt * 16 * 80);
                LDSM4(al[mt][0], al[mt][1], al[mt][2], al[mt][3],
                      base + TILE_B + aoff + mt * 16 * 80);
            }
#pragma unroll
            for (int np = 0; np < 2; np++)
                LDSM4(bh[np][0], bh[np][1], bh[np][2], bh[np][3],
                      base + 2 * TILE_B + boff + np * 16 * 80);
#pragma unroll
            for (int mt = 0; mt < 4; mt++)
#pragma unroll
                for (int np = 0; np < 2; np++) {
                    MMA16816F(acc[mt][np * 2 + 0], ah[mt], bh[np][0], bh[np][1]);
                    MMA16816F(acc[mt][np * 2 + 1], ah[mt], bh[np][2], bh[np][3]);
                }
#pragma unroll
            for (int mt = 0; mt < 4; mt++)
#pragma unroll
                for (int np = 0; np < 2; np++) {
                    MMA16816F(acc[mt][np * 2 + 0], al[mt], bh[np][0], bh[np][1]);
                    MMA16816F(acc[mt][np * 2 + 1], al[mt], bh[np][2], bh[np][3]);
                }
        }
    }

    const int g = lane >> 2, c2 = lane & 3;
#pragma unroll
    for (int mt = 0; mt < 4; mt++) {
        const int row = m0 + wm + mt * 16 + g;
#pragma unroll
        for (int nt = 0; nt < 4; nt++) {
            const int col = n0 + wn + nt * 8 + c2 * 2;
            *(float2*)&C[(size_t)row * N + col] =
                make_float2(acc[mt][nt][0], acc[mt][nt][1]);
            *(float2*)&C[(size_t)(row + 8) * N + col] =
                make_float2(acc[mt][nt][2], acc[mt][nt][3]);
        }
    }
}

// ---------------- tensor-core flash attention (unchanged from R8) ----------------
#define FQ_H 0
#define FQ_L 18432
#define FKV  36864
#define FKV_STRIDE 27648
#define F_SMEM 92160

__global__ __launch_bounds__(256, 2) void flash_mma(
    const __nv_bfloat16* __restrict__ Qhi, const __nv_bfloat16* __restrict__ Qlo,
    const __nv_bfloat16* __restrict__ Khi, const __nv_bfloat16* __restrict__ Klo,
    const __half* __restrict__ Vh,
    __half* __restrict__ Ohf, __half* __restrict__ Olf) {
    extern __shared__ char smem[];
    const uint32_t sb = smem_u32(smem);
    const int tid = threadIdx.x;
    const int lane = tid & 31;
    const int w = tid >> 5;
    const int ib = gridDim.x - 1 - blockIdx.x;
    const int qh = blockIdx.y;
    const int kh = qh >> 2;
    const int qbase = ib * 128;

#pragma unroll
    for (int i = 0; i < 8; i++) {
        int idx = tid + i * 256;
        int sub = idx >> 10, r = (idx >> 3) & 127, q = idx & 7;
        const __nv_bfloat16* src = (sub ? Qlo : Qhi) + (size_t)(qbase + r) * HID + qh * 64 + q * 8;
        CP_ASYNC16(sb + sub * 18432 + r * 144 + q * 16, src);
    }
    CP_COMMIT();

#pragma unroll
    for (int i = 0; i < 6; i++) {
        int idx = tid + i * 256;
        int sub = idx >> 9, r = (idx >> 3) & 63, q = idx & 7;
        const uint16_t* base = (sub == 0) ? (const uint16_t*)Khi
                               : (sub == 1) ? (const uint16_t*)Klo : (const uint16_t*)Vh;
        const void* src = base + (size_t)r * KVD + kh * 64 + q * 8;
        CP_ASYNC16(sb + FKV + sub * 9216 + r * 144 + q * 16, src);
    }
    CP_COMMIT();

    const int a_row = lane & 15, a_kh = lane >> 4;
    const int b_n = (lane & 7) + ((lane >> 4) << 3), b_kh = (lane >> 3) & 1;
    const int v_k = (lane & 7) + ((lane >> 3) & 1) * 8, v_n = (lane >> 4) * 8;
    const int g = lane >> 2, tg = lane & 3;

    float o[8][4];
#pragma unroll
    for (int nt = 0; nt < 8; nt++)
#pragma unroll
        for (int r = 0; r < 4; r++) o[nt][r] = 0.f;
    float m0 = -1e30f, m1 = -1e30f, l0 = 0.f, l1 = 0.f;

    const int jbmax = 2 * ib + 1;
    for (int jb = 0; jb <= jbmax; jb++) {
        const uint32_t kvb = sb + FKV + (jb & 1) * FKV_STRIDE;
        __syncthreads();
        if (jb < jbmax) {
            const uint32_t nb = sb + FKV + ((jb + 1) & 1) * FKV_STRIDE;
#pragma unroll
            for (int i = 0; i < 6; i++) {
                int idx = tid + i * 256;
                int sub = idx >> 9, r = (idx >> 3) & 63, q = idx & 7;
                const uint16_t* base = (sub == 0) ? (const uint16_t*)Khi
                                       : (sub == 1) ? (const uint16_t*)Klo : (const uint16_t*)Vh;
                const void* src = base + (size_t)((jb + 1) * 64 + r) * KVD + kh * 64 + q * 8;
                CP_ASYNC16(nb + sub * 9216 + r * 144 + q * 16, src);
            }
            CP_COMMIT();
            CP_WAIT1();
        } else {
            CP_WAIT0();
        }
        __syncthreads();

        // S = Q K^T (bf16 3-pass, pass-major)
        float s[8][4];
#pragma unroll
        for (int nt = 0; nt < 8; nt++)
#pragma unroll
            for (int r = 0; r < 4; r++) s[nt][r] = 0.f;
#pragma unroll
        for (int kc = 0; kc < 4; kc++) {
            uint32_t ah[4], al[4];
            const uint32_t aoff = (w * 16 + a_row) * 144 + (kc * 16 + a_kh * 8) * 2;
            LDSM4(ah[0], ah[1], ah[2], ah[3], sb + FQ_H + aoff);
            LDSM4(al[0], al[1], al[2], al[3], sb + FQ_L + aoff);
#pragma unroll
            for (int n2p = 0; n2p < 2; n2p++) {
                uint32_t bh[2][4], bl[2][4];
#pragma unroll
                for (int j = 0; j < 2; j++) {
                    const int n2 = n2p * 2 + j;
                    const uint32_t boff = (n2 * 16 + b_n) * 144 + (kc * 16 + b_kh * 8) * 2;
                    LDSM4(bh[j][0], bh[j][1], bh[j][2], bh[j][3], kvb + boff);
                    LDSM4(bl[j][0], bl[j][1], bl[j][2], bl[j][3], kvb + 9216 + boff);
                }
#pragma unroll
                for (int j = 0; j < 2; j++) {
                    const int n2 = n2p * 2 + j;
                    MMA16816(s[n2 * 2 + 0], ah, bh[j][0], bh[j][1]);
                    MMA16816(s[n2 * 2 + 1], ah, bh[j][2], bh[j][3]);
                }
#pragma unroll
                for (int j = 0; j < 2; j++) {
                    const int n2 = n2p * 2 + j;
                    MMA16816(s[n2 * 2 + 0], ah, bl[j][0], bl[j][1]);
                    MMA16816(s[n2 * 2 + 1], ah, bl[j][2], bl[j][3]);
                }
#pragma unroll
                for (int j = 0; j < 2; j++) {
                    const int n2 = n2p * 2 + j;
                    MMA16816(s[n2 * 2 + 0], al, bh[j][0], bh[j][1]);
                    MMA16816(s[n2 * 2 + 1], al, bh[j][2], bh[j][3]);
                }
            }
        }

        if (jb >= 2 * ib) {
            const int row0 = qbase + w * 16 + g;
            const int row1 = row0 + 8;
#pragma unroll
            for (int nt = 0; nt < 8; nt++) {
                const int col = jb * 64 + nt * 8 + tg * 2;
                if (col > row0) s[nt][0] = -1e30f;
                if (col + 1 > row0) s[nt][1] = -1e30f;
                if (col > row1) s[nt][2] = -1e30f;
                if (col + 1 > row1) s[nt][3] = -1e30f;
            }
        }

        float mx0 = -1e30f, mx1 = -1e30f;
#pragma unroll
        for (int nt = 0; nt < 8; nt++) {
            mx0 = fmaxf(mx0, fmaxf(s[nt][0], s[nt][1]));
            mx1 = fmaxf(mx1, fmaxf(s[nt][2], s[nt][3]));
        }
        mx0 = fmaxf(mx0, __shfl_xor_sync(0xffffffff, mx0, 1));
        mx0 = fmaxf(mx0, __shfl_xor_sync(0xffffffff, mx0, 2));
        mx1 = fmaxf(mx1, __shfl_xor_sync(0xffffffff, mx1, 1));
        mx1 = fmaxf(mx1, __shfl_xor_sync(0xffffffff, mx1, 2));
        const float mn0 = fmaxf(m0, mx0), mn1 = fmaxf(m1, mx1);
        const float al0 = __expf(m0 - mn0), al1 = __expf(m1 - mn1);
        m0 = mn0; m1 = mn1;

        float rs0 = 0.f, rs1 = 0.f;
#pragma unroll
        for (int nt = 0; nt < 8; nt++) {
            s[nt][0] = __expf(s[nt][0] - mn0);
            s[nt][1] = __expf(s[nt][1] - mn0);
            s[nt][2] = __expf(s[nt][2] - mn1);
            s[nt][3] = __expf(s[nt][3] - mn1);
            rs0 += s[nt][0] + s[nt][1];
            rs1 += s[nt][2] + s[nt][3];
            o[nt][0] *= al0; o[nt][1] *= al0;
            o[nt][2] *= al1; o[nt][3] *= al1;
        }
        rs0 += __shfl_xor_sync(0xffffffff, rs0, 1);
        rs0 += __shfl_xor_sync(0xffffffff, rs0, 2);
        rs1 += __shfl_xor_sync(0xffffffff, rs1, 1);
        rs1 += __shfl_xor_sync(0xffffffff, rs1, 2);
        l0 = l0 * al0 + rs0;
        l1 = l1 * al1 + rs1;

        // O += P @ V : fp16 2-pass
#pragma unroll
        for (int kc2 = 0; kc2 < 4; kc2++) {
            uint32_t aph[4], apl[4];
            pack_hl16(s[2 * kc2][0], s[2 * kc2][1], aph[0], apl[0]);
            pack_hl16(s[2 * kc2][2], s[2 * kc2][3], aph[1], apl[1]);
            pack_hl16(s[2 * kc2 + 1][0], s[2 * kc2 + 1][1], aph[2], apl[2]);
            pack_hl16(s[2 * kc2 + 1][2], s[2 * kc2 + 1][3], aph[3], apl[3]);
#pragma unroll
            for (int n2p = 0; n2p < 2; n2p++) {
                uint32_t vh[2][4];
#pragma unroll
                for (int j = 0; j < 2; j++) {
                    const int n2 = n2p * 2 + j;
                    const uint32_t voff = (kc2 * 16 + v_k) * 144 + (n2 * 16 + v_n) * 2;
                    LDSM4T(vh[j][0], vh[j][1], vh[j][2], vh[j][3], kvb + 2 * 9216 + voff);
                }
#pragma unroll
                for (int j = 0; j < 2; j++) {
                    const int n2 = n2p * 2 + j;
                    MMA16816F(o[n2 * 2 + 0], aph, vh[j][0], vh[j][1]);
                    MMA16816F(o[n2 * 2 + 1], aph, vh[j][2], vh[j][3]);
                }
#pragma unroll
                for (int j = 0; j < 2; j++) {
                    const int n2 = n2p * 2 + j;
                    MMA16816F(o[n2 * 2 + 0], apl, vh[j][0], vh[j][1]);
                    MMA16816F(o[n2 * 2 + 1], apl, vh[j][2], vh[j][3]);
                }
            }
        }
    }

    const float il0 = 1.0f / l0, il1 = 1.0f / l1;
    const int row0 = qbase + w * 16 + g;
#pragma unroll
    for (int nt = 0; nt < 8; nt++) {
        const int col = qh * 64 + nt * 8 + tg * 2;
        uint32_t h, l;
        pack_hl16(o[nt][0] * il0, o[nt][1] * il0, h, l);
        *(uint32_t*)&Ohf[(size_t)row0 * HID + col] = h;
        *(uint32_t*)&Olf[(size_t)row0 * HID + col] = l;
        pack_hl16(o[nt][2] * il1, o[nt][3] * il1, h, l);
        *(uint32_t*)&Ohf[(size_t)(row0 + 8) * HID + col] = h;
        *(uint32_t*)&Olf[(size_t)(row0 + 8) * HID + col] = l;
    }
}

// ---------------------------------------------------------------------------
extern "C" void kernel_launch(void* const* d_in, const int* in_sizes, int n_in,
                              void* d_out, int out_size) {
    const float* x        = (const float*)d_in[0];
    const float* q_proj   = (const float*)d_in[1];
    const float* k_proj   = (const float*)d_in[2];
    const float* v_proj   = (const float*)d_in[3];
    const float* o_proj   = (const float*)d_in[4];
    const float* inv_freq = (const float*)d_in[5];
    float* out = (float*)d_out;

    float *QKVb;
    __nv_bfloat16 *Khi, *Klo, *Qbh, *Qbl;
    __half *Axh, *Axl, *Ohf, *Olf, *Wh, *Vh;
    float2* sc;
    cudaGetSymbolAddress((void**)&QKVb, g_QKV);
    cudaGetSymbolAddress((void**)&Axh, g_Axh);
    cudaGetSymbolAddress((void**)&Axl, g_Axl);
    cudaGetSymbolAddress((void**)&Ohf, g_Ohf);
    cudaGetSymbolAddress((void**)&Olf, g_Olf);
    cudaGetSymbolAddress((void**)&Wh, g_Wh);
    cudaGetSymbolAddress((void**)&Khi, g_Khi);
    cudaGetSymbolAddress((void**)&Klo, g_Klo);
    cudaGetSymbolAddress((void**)&Vh, g_Vh);
    cudaGetSymbolAddress((void**)&sc, g_sc);
    // Q bf16 hi/lo reuse the fp16 x buffers' storage is NOT safe (different type &
    // lifetime overlaps rope read of QKVb only) — use dedicated reuse: after QKV GEMM,
    // Axh/Axl are dead, reinterpret as bf16 Q buffers (same 8 MB size each).
    Qbh = (__nv_bfloat16*)Axh;
    Qbl = (__nv_bfloat16*)Axl;

    cudaFuncSetAttribute(gemm_mma2, cudaFuncAttributeMaxDynamicSharedMemorySize, G2_SMEM);
    cudaFuncSetAttribute(flash_mma, cudaFuncAttributeMaxDynamicSharedMemorySize, F_SMEM);

    const int convBlocks = (SEQ * HID / 4) / 256;

    convert_hl16<<<convBlocks, 256>>>(x, Axh, Axl);
    transpose_all16<<<dim3(160, HID / 32), 256>>>(q_proj, k_proj, v_proj, o_proj, Wh);
    sc_init<<<SEQ * 32 / 256, 256>>>(inv_freq, sc);

    // fused QKV projection (fp16 2-pass)
    gemm_mma2<<<dim3(QKVN / 128, SEQ / 128), 256, G2_SMEM>>>(Axh, Axl, Wh, QKVb,
                                                             SEQ, QKVN, HID);

    // RoPE + splits (Axh/Axl dead after GEMM -> reused as Q bf16 hi/lo)
    rope_conv<<<SEQ * NQH / 8, 256>>>(QKVb, Qbh, Qbl, sc, NQH, 0.125f, QKVN, 0);
    rope_conv<<<SEQ * NKH / 8, 256>>>(QKVb, Khi, Klo, sc, NKH, 1.0f, QKVN, HID);
    convert_h16_strided<<<(SEQ * KVD / 4) / 256, 256>>>(QKVb, Vh, QKVN, HID + KVD, KVD);

    // flash attention (S bf16 3-pass, PV fp16 2-pass)
    flash_mma<<<dim3(SEQ / 128, NQH), 256, F_SMEM>>>(Qbh, Qbl, Khi, Klo, Vh, Ohf, Olf);

    // out = O @ o_proj (fp16 2-pass)
    gemm_mma2<<<dim3(HID / 128, SEQ / 128), 256, G2_SMEM>>>(Ohf, Olf, Wh + (size_t)QKVN * HID,
                                                            out, SEQ, HID, HID);
}

// round 12
// speedup vs baseline: 1.2509x; 1.0627x over previous
#include <cuda_runtime.h>
#include <cuda_bf16.h>
#include <cuda_fp16.h>
#include <math.h>
#include <cstdint>

#define SEQ 2048
#define HID 2048
#define KVD 512
#define QKVN 3072
#define WROWS 5120
#define NQH 32
#define NKH 8

// ---------------- scratch (no allocations allowed) ----------------
__device__ float g_QKV[SEQ * QKVN];
__device__ __half g_Axh[SEQ * HID];          // x fp16 hi (reused: Q fp16 hi after QKV)
__device__ __half g_Axl[SEQ * HID];          // x fp16 lo (reused: Q fp16 lo)
__device__ __half g_Ohf[SEQ * HID];
__device__ __half g_Olf[SEQ * HID];
__device__ __half g_Wh[WROWS * HID];         // transposed q|k|v|o weights, fp16 hi
__device__ __half g_Kh[SEQ * KVD];           // K fp16 (post-rope)
__device__ __half g_Vh[SEQ * KVD];           // V fp16
__device__ float2 g_sc[SEQ * 32];            // sincos LUT

// ---------------- helpers ----------------
__device__ __forceinline__ uint32_t smem_u32(const void* p) {
    uint32_t a;
    asm("{ .reg .u64 t; cvta.to.shared.u64 t, %1; cvt.u32.u64 %0, t; }" : "=r"(a) : "l"(p));
    return a;
}

#define LDSM4(r0, r1, r2, r3, addr) \
    asm volatile("ldmatrix.sync.aligned.m8n8.x4.shared.b16 {%0,%1,%2,%3}, [%4];" \
        : "=r"(r0), "=r"(r1), "=r"(r2), "=r"(r3) : "r"(addr))

#define LDSM4T(r0, r1, r2, r3, addr) \
    asm volatile("ldmatrix.sync.aligned.m8n8.x4.trans.shared.b16 {%0,%1,%2,%3}, [%4];" \
        : "=r"(r0), "=r"(r1), "=r"(r2), "=r"(r3) : "r"(addr))

#define MMA16816F(d, a, b0, b1) \
    asm volatile("mma.sync.aligned.m16n8k16.row.col.f32.f16.f16.f32 " \
        "{%0,%1,%2,%3},{%4,%5,%6,%7},{%8,%9},{%0,%1,%2,%3};" \
        : "+f"((d)[0]), "+f"((d)[1]), "+f"((d)[2]), "+f"((d)[3]) \
        : "r"((a)[0]), "r"((a)[1]), "r"((a)[2]), "r"((a)[3]), "r"(b0), "r"(b1))

#define CP_ASYNC16(dst, src) \
    asm volatile("cp.async.cg.shared.global [%0], [%1], 16;" :: "r"(dst), "l"(src))
#define CP_COMMIT() asm volatile("cp.async.commit_group;" ::: "memory")
#define CP_WAIT0()  asm volatile("cp.async.wait_group 0;" ::: "memory")
#define CP_WAIT1()  asm volatile("cp.async.wait_group 1;" ::: "memory")

// ---------------- elementwise kernels ----------------
__device__ __forceinline__ void pack_hl16(float p0, float p1, uint32_t& hi, uint32_t& lo) {
    __half2 h = __floats2half2_rn(p0, p1);
    hi = *reinterpret_cast<uint32_t*>(&h);
    __half2 l = __floats2half2_rn(p0 - __half2float(__low2half(h)),
                                  p1 - __half2float(__high2half(h)));
    lo = *reinterpret_cast<uint32_t*>(&l);
}

// fp32 -> fp16 hi/lo
__global__ __launch_bounds__(256) void convert_hl16(const float* __restrict__ X,
                                                    __half* __restrict__ hi,
                                                    __half* __restrict__ lo) {
    int i = blockIdx.x * 256 + threadIdx.x;
    float4 v = *(const float4*)(X + (size_t)i * 4);
    uint32_t h0, l0, h1, l1;
    pack_hl16(v.x, v.y, h0, l0);
    pack_hl16(v.z, v.w, h1, l1);
    *(uint2*)(hi + (size_t)i * 4) = make_uint2(h0, h1);
    *(uint2*)(lo + (size_t)i * 4) = make_uint2(l0, l1);
}

// strided fp32 -> fp16 (hi only) for V
__global__ __launch_bounds__(256) void convert_h16_strided(const float* __restrict__ X,
                                                           __half* __restrict__ h,
                                                           int ld, int col0, int cols) {
    int i = blockIdx.x * 256 + threadIdx.x;
    int r = i / (cols / 4), q = i % (cols / 4);
    float4 v = *(const float4*)(X + (size_t)r * ld + col0 + q * 4);
    __half2 a = __floats2half2_rn(v.x, v.y);
    __half2 b = __floats2half2_rn(v.z, v.w);
    *(uint2*)(h + (size_t)r * cols + q * 4) =
        make_uint2(*reinterpret_cast<uint32_t*>(&a), *reinterpret_cast<uint32_t*>(&b));
}

// fused transpose: all 4 weight matrices -> fp16 hi into Wh [WROWS, HID]
__global__ __launch_bounds__(256) void transpose_all16(const float* __restrict__ Wq,
                                                       const float* __restrict__ Wk,
                                                       const float* __restrict__ Wv,
                                                       const float* __restrict__ Wo,
                                                       __half* __restrict__ toh) {
    __shared__ float t[32][33];
    int bx = blockIdx.x;
    const float* W;
    int N, nblk, dstoff;
    if (bx < 64)       { W = Wq; N = HID; nblk = bx;      dstoff = 0; }
    else if (bx < 80)  { W = Wk; N = KVD; nblk = bx - 64; dstoff = HID; }
    else if (bx < 96)  { W = Wv; N = KVD; nblk = bx - 80; dstoff = HID + KVD; }
    else               { W = Wo; N = HID; nblk = bx - 96; dstoff = QKVN; }
    int tx = threadIdx.x & 31, ty = threadIdx.x >> 5;
    int k0 = blockIdx.y * 32, n0 = nblk * 32;
#pragma unroll
    for (int i = 0; i < 4; i++)
        t[ty + i * 8][tx] = W[(size_t)(k0 + ty + i * 8) * N + n0 + tx];
    __syncthreads();
#pragma unroll
    for (int i = 0; i < 4; i++) {
        float v = t[tx][ty + i * 8];
        toh[(size_t)(dstoff + n0 + ty + i * 8) * HID + k0 + tx] = __float2half_rn(v);
    }
}

// sincos LUT init
__global__ __launch_bounds__(256) void sc_init(const float* __restrict__ inv_freq,
                                               float2* __restrict__ sc) {
    int i = blockIdx.x * 256 + threadIdx.x;
    int s = i >> 5, j = i & 31;
    float angle = (float)s * inv_freq[j];
    sc[i] = make_float2(sinf(angle), cosf(angle));
}

// RoPE + scale -> fp16 hi/lo (for Q)
__global__ __launch_bounds__(256) void rope_q16(const float* __restrict__ X,
                                                __half* __restrict__ hi,
                                                __half* __restrict__ lo,
                                                const float2* __restrict__ sc,
                                                int heads, float scale, int ld, int col0) {
    int idx = blockIdx.x * 8 + (threadIdx.x >> 5);
    int j = threadIdx.x & 31;
    int s = idx / heads;
    int h = idx - s * heads;
    const float* p = X + (size_t)s * ld + col0 + h * 64;
    float2 snc = sc[s * 32 + j];
    float a = p[j], b = p[32 + j];
    float r0 = (a * snc.y + b * snc.x) * scale;
    float r1 = (a * snc.x - b * snc.y) * scale;
    size_t o = (size_t)s * heads * 64 + h * 64;
    __half h0 = __float2half_rn(r0);
    __half h1 = __float2half_rn(r1);
    hi[o + j] = h0;
    hi[o + 32 + j] = h1;
    lo[o + j] = __float2half_rn(r0 - __half2float(h0));
    lo[o + 32 + j] = __float2half_rn(r1 - __half2float(h1));
}

// RoPE -> fp16 single (for K)
__global__ __launch_bounds__(256) void rope_k16(const float* __restrict__ X,
                                                __half* __restrict__ out,
                                                const float2* __restrict__ sc,
                                                int heads, int ld, int col0) {
    int idx = blockIdx.x * 8 + (threadIdx.x >> 5);
    int j = threadIdx.x & 31;
    int s = idx / heads;
    int h = idx - s * heads;
    const float* p = X + (size_t)s * ld + col0 + h * 64;
    float2 snc = sc[s * 32 + j];
    float a = p[j], b = p[32 + j];
    size_t o = (size_t)s * heads * 64 + h * 64;
    out[o + j] = __float2half_rn(a * snc.y + b * snc.x);
    out[o + 32 + j] = __float2half_rn(a * snc.x - b * snc.y);
}

// ---------------- fp16 2-pass GEMM (QKV + O projection), 128x128 occ 2 ----------------
#define TILE_B 10240
#define BUF2_B 30720
#define G2_SMEM (2 * BUF2_B)

__device__ __forceinline__ void tile_async(uint32_t dst, const void* src_,
                                           int ldk, int tid) {
    const __half* src = (const __half*)src_;
#pragma unroll
    for (int t = 0; t < 2; t++) {
        int i = tid + t * 256;
        int r = i >> 2, q = i & 3;
        CP_ASYNC16(dst + r * 80 + q * 16, src + (size_t)r * ldk + q * 8);
    }
}

__global__ __launch_bounds__(256, 2) void gemm_mma2(
    const __half* __restrict__ Ahi, const __half* __restrict__ Alo,
    const __half* __restrict__ Bh,
    float* __restrict__ C, int M, int N, int K) {
    extern __shared__ char smem[];
    const uint32_t sb = smem_u32(smem);
    const int tid = threadIdx.x;
    const int w = tid >> 5;
    const int lane = tid & 31;
    const int wm = (w & 1) * 64;
    const int wn = (w >> 1) * 32;
    const int m0 = blockIdx.y * 128;
    const int n0 = blockIdx.x * 128;

    const int a_row = lane & 15;
    const int a_kh = (lane >> 4) & 1;
    const int b_n = (lane & 7) + ((lane >> 4) << 3);
    const int b_kh = (lane >> 3) & 1;

    float acc[4][4][4];
#pragma unroll
    for (int i = 0; i < 4; i++)
#pragma unroll
        for (int j = 0; j < 4; j++)
#pragma unroll
            for (int r = 0; r < 4; r++) acc[i][j][r] = 0.f;

    const int NC = K >> 5;
    {
        const size_t ak = (size_t)m0 * K;
        const size_t bk = (size_t)n0 * K;
        tile_async(sb,              Ahi + ak, K, tid);
        tile_async(sb + TILE_B,     Alo + ak, K, tid);
        tile_async(sb + 2 * TILE_B, Bh + bk, K, tid);
        CP_COMMIT();
    }

    for (int c = 0; c < NC; c++) {
        CP_WAIT0();
        __syncthreads();
        if (c + 1 < NC) {
            const uint32_t nb = sb + ((c + 1) & 1) * BUF2_B;
            const size_t ak = (size_t)m0 * K + (size_t)(c + 1) * 32;
            const size_t bk = (size_t)n0 * K + (size_t)(c + 1) * 32;
            tile_async(nb,              Ahi + ak, K, tid);
            tile_async(nb + TILE_B,     Alo + ak, K, tid);
            tile_async(nb + 2 * TILE_B, Bh + bk, K, tid);
            CP_COMMIT();
        }
        const uint32_t base = sb + (c & 1) * BUF2_B;

#pragma unroll
        for (int ks = 0; ks < 32; ks += 16) {
            uint32_t ah[4][4], al[4][4], bh[2][4];
            const uint32_t aoff = (uint32_t)((wm + a_row) * 80 + (ks + a_kh * 8) * 2);
            const uint32_t boff = (uint32_t)((wn + b_n) * 80 + (ks + b_kh * 8) * 2);
#pragma unroll
            for (int mt = 0; mt < 4; mt++) {
                LDSM4(ah[mt][0], ah[mt][1], ah[mt][2], ah[mt][3],
                      base + aoff + mt * 16 * 80);
                LDSM4(al[mt][0], al[mt][1], al[mt][2], al[mt][3],
                      base + TILE_B + aoff + mt * 16 * 80);
            }
#pragma unroll
            for (int np = 0; np < 2; np++)
                LDSM4(bh[np][0], bh[np][1], bh[np][2], bh[np][3],
                      base + 2 * TILE_B + boff + np * 16 * 80);
#pragma unroll
            for (int mt = 0; mt < 4; mt++)
#pragma unroll
                for (int np = 0; np < 2; np++) {
                    MMA16816F(acc[mt][np * 2 + 0], ah[mt], bh[np][0], bh[np][1]);
                    MMA16816F(acc[mt][np * 2 + 1], ah[mt], bh[np][2], bh[np][3]);
                }
#pragma unroll
            for (int mt = 0; mt < 4; mt++)
#pragma unroll
                for (int np = 0; np < 2; np++) {
                    MMA16816F(acc[mt][np * 2 + 0], al[mt], bh[np][0], bh[np][1]);
                    MMA16816F(acc[mt][np * 2 + 1], al[mt], bh[np][2], bh[np][3]);
                }
        }
    }

    const int g = lane >> 2, c2 = lane & 3;
#pragma unroll
    for (int mt = 0; mt < 4; mt++) {
        const int row = m0 + wm + mt * 16 + g;
#pragma unroll
        for (int nt = 0; nt < 4; nt++) {
            const int col = n0 + wn + nt * 8 + c2 * 2;
            *(float2*)&C[(size_t)row * N + col] =
                make_float2(acc[mt][nt][0], acc[mt][nt][1]);
            *(float2*)&C[(size_t)(row + 8) * N + col] =
                make_float2(acc[mt][nt][2], acc[mt][nt][3]);
        }
    }
}

// ---------------- all-fp16 tensor-core flash attention ----------------
// smem: Qhi(0) Qlo(18432) | KV buffers at 36864: Kh(0) Vh(9216), stride 18432
#define FQ_H 0
#define FQ_L 18432
#define FKV  36864
#define FKV_STRIDE 18432
#define F_SMEM 73728

__global__ __launch_bounds__(256, 2) void flash_mma(
    const __half* __restrict__ Qhi, const __half* __restrict__ Qlo,
    const __half* __restrict__ Kh, const __half* __restrict__ Vh,
    __half* __restrict__ Ohf, __half* __restrict__ Olf) {
    extern __shared__ char smem[];
    const uint32_t sb = smem_u32(smem);
    const int tid = threadIdx.x;
    const int lane = tid & 31;
    const int w = tid >> 5;
    const int ib = gridDim.x - 1 - blockIdx.x;
    const int qh = blockIdx.y;
    const int kh = qh >> 2;
    const int qbase = ib * 128;

    // Q tile (fp16 hi/lo)
#pragma unroll
    for (int i = 0; i < 8; i++) {
        int idx = tid + i * 256;
        int sub = idx >> 10, r = (idx >> 3) & 127, q = idx & 7;
        const __half* src = (sub ? Qlo : Qhi) + (size_t)(qbase + r) * HID + qh * 64 + q * 8;
        CP_ASYNC16(sb + sub * 18432 + r * 144 + q * 16, src);
    }
    CP_COMMIT();

    // KV chunk 0 -> buf 0 (K, V)
#pragma unroll
    for (int i = 0; i < 4; i++) {
        int idx = tid + i * 256;
        int sub = idx >> 9, r = (idx >> 3) & 63, q = idx & 7;
        const __half* base = sub ? Vh : Kh;
        CP_ASYNC16(sb + FKV + sub * 9216 + r * 144 + q * 16,
                   base + (size_t)r * KVD + kh * 64 + q * 8);
    }
    CP_COMMIT();

    const int a_row = lane & 15, a_kh = lane >> 4;
    const int b_n = (lane & 7) + ((lane >> 4) << 3), b_kh = (lane >> 3) & 1;
    const int v_k = (lane & 7) + ((lane >> 3) & 1) * 8, v_n = (lane >> 4) * 8;
    const int g = lane >> 2, tg = lane & 3;

    float o[8][4];
#pragma unroll
    for (int nt = 0; nt < 8; nt++)
#pragma unroll
        for (int r = 0; r < 4; r++) o[nt][r] = 0.f;
    float m0 = -1e30f, m1 = -1e30f, l0 = 0.f, l1 = 0.f;

    const int jbmax = 2 * ib + 1;
    for (int jb = 0; jb <= jbmax; jb++) {
        const uint32_t kvb = sb + FKV + (jb & 1) * FKV_STRIDE;
        __syncthreads();
        if (jb < jbmax) {
            const uint32_t nb = sb + FKV + ((jb + 1) & 1) * FKV_STRIDE;
#pragma unroll
            for (int i = 0; i < 4; i++) {
                int idx = tid + i * 256;
                int sub = idx >> 9, r = (idx >> 3) & 63, q = idx & 7;
                const __half* base = sub ? Vh : Kh;
                CP_ASYNC16(nb + sub * 9216 + r * 144 + q * 16,
                           base + (size_t)((jb + 1) * 64 + r) * KVD + kh * 64 + q * 8);
            }
            CP_COMMIT();
            CP_WAIT1();
        } else {
            CP_WAIT0();
        }
        __syncthreads();

        // S = Q K^T (fp16 2-pass: (Qh+Ql) x Kh)
        float s[8][4];
#pragma unroll
        for (int nt = 0; nt < 8; nt++)
#pragma unroll
            for (int r = 0; r < 4; r++) s[nt][r] = 0.f;
#pragma unroll
        for (int kc = 0; kc < 4; kc++) {
            uint32_t ah[4], al[4];
            const uint32_t aoff = (w * 16 + a_row) * 144 + (kc * 16 + a_kh * 8) * 2;
            LDSM4(ah[0], ah[1], ah[2], ah[3], sb + FQ_H + aoff);
            LDSM4(al[0], al[1], al[2], al[3], sb + FQ_L + aoff);
#pragma unroll
            for (int n2p = 0; n2p < 2; n2p++) {
                uint32_t bh[2][4];
#pragma unroll
                for (int j = 0; j < 2; j++) {
                    const int n2 = n2p * 2 + j;
                    const uint32_t boff = (n2 * 16 + b_n) * 144 + (kc * 16 + b_kh * 8) * 2;
                    LDSM4(bh[j][0], bh[j][1], bh[j][2], bh[j][3], kvb + boff);
                }
#pragma unroll
                for (int j = 0; j < 2; j++) {
                    const int n2 = n2p * 2 + j;
                    MMA16816F(s[n2 * 2 + 0], ah, bh[j][0], bh[j][1]);
                    MMA16816F(s[n2 * 2 + 1], ah, bh[j][2], bh[j][3]);
                }
#pragma unroll
                for (int j = 0; j < 2; j++) {
                    const int n2 = n2p * 2 + j;
                    MMA16816F(s[n2 * 2 + 0], al, bh[j][0], bh[j][1]);
                    MMA16816F(s[n2 * 2 + 1], al, bh[j][2], bh[j][3]);
                }
            }
        }

        if (jb >= 2 * ib) {
            const int row0 = qbase + w * 16 + g;
            const int row1 = row0 + 8;
#pragma unroll
            for (int nt = 0; nt < 8; nt++) {
                const int col = jb * 64 + nt * 8 + tg * 2;
                if (col > row0) s[nt][0] = -1e30f;
                if (col + 1 > row0) s[nt][1] = -1e30f;
                if (col > row1) s[nt][2] = -1e30f;
                if (col + 1 > row1) s[nt][3] = -1e30f;
            }
        }

        float mx0 = -1e30f, mx1 = -1e30f;
#pragma unroll
        for (int nt = 0; nt < 8; nt++) {
            mx0 = fmaxf(mx0, fmaxf(s[nt][0], s[nt][1]));
            mx1 = fmaxf(mx1, fmaxf(s[nt][2], s[nt][3]));
        }
        mx0 = fmaxf(mx0, __shfl_xor_sync(0xffffffff, mx0, 1));
        mx0 = fmaxf(mx0, __shfl_xor_sync(0xffffffff, mx0, 2));
        mx1 = fmaxf(mx1, __shfl_xor_sync(0xffffffff, mx1, 1));
        mx1 = fmaxf(mx1, __shfl_xor_sync(0xffffffff, mx1, 2));
        const float mn0 = fmaxf(m0, mx0), mn1 = fmaxf(m1, mx1);
        const float al0 = __expf(m0 - mn0), al1 = __expf(m1 - mn1);
        m0 = mn0; m1 = mn1;

        float rs0 = 0.f, rs1 = 0.f;
#pragma unroll
        for (int nt = 0; nt < 8; nt++) {
            s[nt][0] = __expf(s[nt][0] - mn0);
            s[nt][1] = __expf(s[nt][1] - mn0);
            s[nt][2] = __expf(s[nt][2] - mn1);
            s[nt][3] = __expf(s[nt][3] - mn1);
            rs0 += s[nt][0] + s[nt][1];
            rs1 += s[nt][2] + s[nt][3];
            o[nt][0] *= al0; o[nt][1] *= al0;
            o[nt][2] *= al1; o[nt][3] *= al1;
        }
        rs0 += __shfl_xor_sync(0xffffffff, rs0, 1);
        rs0 += __shfl_xor_sync(0xffffffff, rs0, 2);
        rs1 += __shfl_xor_sync(0xffffffff, rs1, 1);
        rs1 += __shfl_xor_sync(0xffffffff, rs1, 2);
        l0 = l0 * al0 + rs0;
        l1 = l1 * al1 + rs1;

        // O += P @ V : fp16 2-pass
#pragma unroll
        for (int kc2 = 0; kc2 < 4; kc2++) {
            uint32_t aph[4], apl[4];
            pack_hl16(s[2 * kc2][0], s[2 * kc2][1], aph[0], apl[0]);
            pack_hl16(s[2 * kc2][2], s[2 * kc2][3], aph[1], apl[1]);
            pack_hl16(s[2 * kc2 + 1][0], s[2 * kc2 + 1][1], aph[2], apl[2]);
            pack_hl16(s[2 * kc2 + 1][2], s[2 * kc2 + 1][3], aph[3], apl[3]);
#pragma unroll
            for (int n2p = 0; n2p < 2; n2p++) {
                uint32_t vh[2][4];
#pragma unroll
                for (int j = 0; j < 2; j++) {
                    const int n2 = n2p * 2 + j;
                    const uint32_t voff = (kc2 * 16 + v_k) * 144 + (n2 * 16 + v_n) * 2;
                    LDSM4T(vh[j][0], vh[j][1], vh[j][2], vh[j][3], kvb + 9216 + voff);
                }
#pragma unroll
                for (int j = 0; j < 2; j++) {
                    const int n2 = n2p * 2 + j;
                    MMA16816F(o[n2 * 2 + 0], aph, vh[j][0], vh[j][1]);
                    MMA16816F(o[n2 * 2 + 1], aph, vh[j][2], vh[j][3]);
                }
#pragma unroll
                for (int j = 0; j < 2; j++) {
                    const int n2 = n2p * 2 + j;
                    MMA16816F(o[n2 * 2 + 0], apl, vh[j][0], vh[j][1]);
                    MMA16816F(o[n2 * 2 + 1], apl, vh[j][2], vh[j][3]);
                }
            }
        }
    }

    const float il0 = 1.0f / l0, il1 = 1.0f / l1;
    const int row0 = qbase + w * 16 + g;
#pragma unroll
    for (int nt = 0; nt < 8; nt++) {
        const int col = qh * 64 + nt * 8 + tg * 2;
        uint32_t h, l;
        pack_hl16(o[nt][0] * il0, o[nt][1] * il0, h, l);
        *(uint32_t*)&Ohf[(size_t)row0 * HID + col] = h;
        *(uint32_t*)&Olf[(size_t)row0 * HID + col] = l;
        pack_hl16(o[nt][2] * il1, o[nt][3] * il1, h, l);
        *(uint32_t*)&Ohf[(size_t)(row0 + 8) * HID + col] = h;
        *(uint32_t*)&Olf[(size_t)(row0 + 8) * HID + col] = l;
    }
}

// ---------------------------------------------------------------------------
extern "C" void kernel_launch(void* const* d_in, const int* in_sizes, int n_in,
                              void* d_out, int out_size) {
    const float* x        = (const float*)d_in[0];
    const float* q_proj   = (const float*)d_in[1];
    const float* k_proj   = (const float*)d_in[2];
    const float* v_proj   = (const float*)d_in[3];
    const float* o_proj   = (const float*)d_in[4];
    const float* inv_freq = (const float*)d_in[5];
    float* out = (float*)d_out;

    float* QKVb;
    __half *Axh, *Axl, *Ohf, *Olf, *Wh, *Kh, *Vh;
    float2* sc;
    cudaGetSymbolAddress((void**)&QKVb, g_QKV);
    cudaGetSymbolAddress((void**)&Axh, g_Axh);
    cudaGetSymbolAddress((void**)&Axl, g_Axl);
    cudaGetSymbolAddress((void**)&Ohf, g_Ohf);
    cudaGetSymbolAddress((void**)&Olf, g_Olf);
    cudaGetSymbolAddress((void**)&Wh, g_Wh);
    cudaGetSymbolAddress((void**)&Kh, g_Kh);
    cudaGetSymbolAddress((void**)&Vh, g_Vh);
    cudaGetSymbolAddress((void**)&sc, g_sc);

    cudaFuncSetAttribute(gemm_mma2, cudaFuncAttributeMaxDynamicSharedMemorySize, G2_SMEM);
    cudaFuncSetAttribute(flash_mma, cudaFuncAttributeMaxDynamicSharedMemorySize, F_SMEM);

    const int convBlocks = (SEQ * HID / 4) / 256;

    convert_hl16<<<convBlocks, 256>>>(x, Axh, Axl);
    transpose_all16<<<dim3(160, HID / 32), 256>>>(q_proj, k_proj, v_proj, o_proj, Wh);
    sc_init<<<SEQ * 32 / 256, 256>>>(inv_freq, sc);

    // fused QKV projection (fp16 2-pass)
    gemm_mma2<<<dim3(QKVN / 128, SEQ / 128), 256, G2_SMEM>>>(Axh, Axl, Wh, QKVb,
                                                             SEQ, QKVN, HID);

    // RoPE + splits (Axh/Axl dead after GEMM -> reused as Q fp16 hi/lo)
    rope_q16<<<SEQ * NQH / 8, 256>>>(QKVb, Axh, Axl, sc, NQH, 0.125f, QKVN, 0);
    rope_k16<<<SEQ * NKH / 8, 256>>>(QKVb, Kh, sc, NKH, QKVN, HID);
    convert_h16_strided<<<(SEQ * KVD / 4) / 256, 256>>>(QKVb, Vh, QKVN, HID + KVD, KVD);

    // all-fp16 flash attention (S 2-pass, PV 2-pass)
    flash_mma<<<dim3(SEQ / 128, NQH), 256, F_SMEM>>>(Axh, Axl, Kh, Vh, Ohf, Olf);

    // out = O @ o_proj (fp16 2-pass)
    gemm_mma2<<<dim3(HID / 128, SEQ / 128), 256, G2_SMEM>>>(Ohf, Olf, Wh + (size_t)QKVN * HID,
                                                            out, SEQ, HID, HID);
}